// round 1
// baseline (speedup 1.0000x reference)
#include <cuda_runtime.h>
#include <cuda_bf16.h>

#define DIMC   256
#define INNER  512
#define HEADS  8
#define DHEAD  64
#define WS     7
#define NTOK   49
#define HW     56
#define NPIX   3136      // 56*56, also 49*64
#define BATCH  16
#define NWIN   64        // 8*8 windows

// ---------------- scratch (device globals; no allocation allowed) ----------
// depthwise+BN outputs, layout [proj][b][c][p]
__device__ __align__(128) float g_y[3L * BATCH * DIMC * NPIX];
// q/k/v in windowed layout [proj][b][h][w][t*64+d]
__device__ __align__(128) float g_qkv[3L * BATCH * INNER * NPIX];
// attention output, layout [b][h*64+d][w*49+t]
__device__ __align__(128) float g_a[(long)BATCH * INNER * NPIX];

// ---------------------------------------------------------------------------
// Kernel 1: depthwise 3x3 conv + BN for q,k,v in one pass over x
// ---------------------------------------------------------------------------
__global__ void dwbn_kernel(const float* __restrict__ x,
    const float* __restrict__ qdw, const float* __restrict__ qg,
    const float* __restrict__ qb,  const float* __restrict__ qm,
    const float* __restrict__ qv,
    const float* __restrict__ kdw, const float* __restrict__ kg,
    const float* __restrict__ kb,  const float* __restrict__ km,
    const float* __restrict__ kv,
    const float* __restrict__ vdw, const float* __restrict__ vg,
    const float* __restrict__ vb,  const float* __restrict__ vm,
    const float* __restrict__ vv)
{
    int idx = blockIdx.x * blockDim.x + threadIdx.x;
    if (idx >= BATCH * DIMC * NPIX) return;
    int p = idx % NPIX;
    int c = (idx / NPIX) % DIMC;
    int b = idx / (NPIX * DIMC);
    int yy = p / HW, xx = p % HW;

    const float* xb = x + ((long)(b * DIMC + c)) * NPIX;
    float aq = 0.f, ak = 0.f, av = 0.f;
    #pragma unroll
    for (int ky = 0; ky < 3; ky++) {
        int iy = yy + ky - 1;
        if (iy < 0 || iy >= HW) continue;
        #pragma unroll
        for (int kx = 0; kx < 3; kx++) {
            int ix = xx + kx - 1;
            if (ix < 0 || ix >= HW) continue;
            float xval = xb[iy * HW + ix];
            int wi = c * 9 + ky * 3 + kx;
            aq += xval * __ldg(&qdw[wi]);
            ak += xval * __ldg(&kdw[wi]);
            av += xval * __ldg(&vdw[wi]);
        }
    }
    float sq = __ldg(&qg[c]) * rsqrtf(__ldg(&qv[c]) + 1e-5f);
    float sk = __ldg(&kg[c]) * rsqrtf(__ldg(&kv[c]) + 1e-5f);
    float sv = __ldg(&vg[c]) * rsqrtf(__ldg(&vv[c]) + 1e-5f);
    float oq = (aq - __ldg(&qm[c])) * sq + __ldg(&qb[c]);
    float ok = (ak - __ldg(&km[c])) * sk + __ldg(&kb[c]);
    float ov = (av - __ldg(&vm[c])) * sv + __ldg(&vb[c]);

    long base = ((long)b * DIMC + c) * NPIX + p;
    const long pstride = (long)BATCH * DIMC * NPIX;
    g_y[base]               = oq;
    g_y[base + pstride]     = ok;
    g_y[base + 2 * pstride] = ov;
}

// ---------------------------------------------------------------------------
// Kernel 2: pointwise conv 256->512 as SGEMM, scatter-store to windowed layout
// grid: (ceil(3136/128)=25, 512/128=4, 48=proj*16+b)
// ---------------------------------------------------------------------------
__global__ __launch_bounds__(256) void gemm_qkv_kernel(
    const float* __restrict__ pwq, const float* __restrict__ pwk,
    const float* __restrict__ pwv)
{
    __shared__ float As[8][128];
    __shared__ float Bs[8][128];

    int z = blockIdx.z;
    int proj = z >> 4;
    int b = z & 15;
    const float* A = (proj == 0) ? pwq : (proj == 1) ? pwk : pwv; // [512,256]
    const float* B = g_y + ((long)proj * BATCH + b) * DIMC * NPIX;

    int m0 = blockIdx.y * 128;
    int n0 = blockIdx.x * 128;
    int tid = threadIdx.x;
    int tx = tid & 15, ty = tid >> 4;
    int arow = tid >> 1, acol = (tid & 1) * 4;
    int brow = tid >> 5, bcol = (tid & 31) * 4;

    float acc[8][8];
    #pragma unroll
    for (int i = 0; i < 8; i++)
        #pragma unroll
        for (int j = 0; j < 8; j++) acc[i][j] = 0.f;

    const int K = DIMC;
    for (int k0 = 0; k0 < K; k0 += 8) {
        float4 a4 = *(const float4*)&A[(long)(m0 + arow) * K + k0 + acol];
        As[acol + 0][arow] = a4.x;
        As[acol + 1][arow] = a4.y;
        As[acol + 2][arow] = a4.z;
        As[acol + 3][arow] = a4.w;
        float4 b4 = make_float4(0.f, 0.f, 0.f, 0.f);
        int n = n0 + bcol;
        if (n < NPIX) b4 = *(const float4*)&B[(long)(k0 + brow) * NPIX + n];
        *(float4*)&Bs[brow][bcol] = b4;
        __syncthreads();

        #pragma unroll
        for (int kk = 0; kk < 8; kk++) {
            float ar[8], br[8];
            *(float4*)(ar)     = *(float4*)&As[kk][ty * 8];
            *(float4*)(ar + 4) = *(float4*)&As[kk][ty * 8 + 4];
            *(float4*)(br)     = *(float4*)&Bs[kk][tx * 8];
            *(float4*)(br + 4) = *(float4*)&Bs[kk][tx * 8 + 4];
            #pragma unroll
            for (int i = 0; i < 8; i++)
                #pragma unroll
                for (int j = 0; j < 8; j++)
                    acc[i][j] += ar[i] * br[j];
        }
        __syncthreads();
    }

    long obase = ((long)proj * BATCH + b) * HEADS;
    #pragma unroll
    for (int mi = 0; mi < 8; mi++) {
        int o = m0 + ty * 8 + mi;
        int h = o >> 6, dd = o & 63;
        long hb = (obase + h) * NWIN;
        #pragma unroll
        for (int ni = 0; ni < 8; ni++) {
            int p = n0 + tx * 8 + ni;
            if (p < NPIX) {
                int yy = p / HW, xx = p % HW;
                int w = (yy / WS) * 8 + (xx / WS);
                int t = (yy % WS) * WS + (xx % WS);
                g_qkv[(hb + w) * (long)NPIX + t * 64 + dd] = acc[mi][ni];
            }
        }
    }
}

// ---------------------------------------------------------------------------
// Kernel 3: windowed attention. one CTA per (b,h,w). 256 threads.
// ---------------------------------------------------------------------------
__global__ __launch_bounds__(256) void attn_kernel(const float* __restrict__ pos_emb)
{
    __shared__ float Qs[NTOK * 64];       // 3136
    __shared__ float KT[64 * 52];         // transposed K, padded rows
    __shared__ float Vs[NTOK * 64];       // 3136
    __shared__ float Ss[NTOK * 50];       // scores, padded rows

    int w = blockIdx.x, h = blockIdx.y, b = blockIdx.z;
    int tid = threadIdx.x;
    const long pstride = (long)BATCH * INNER * NPIX;
    long base = (((long)b * HEADS + h) * NWIN + w) * NPIX;
    const float* gq = g_qkv + base;
    const float* gk = g_qkv + base + pstride;
    const float* gv = g_qkv + base + 2 * pstride;

    for (int i = tid; i < NTOK * 64; i += 256) {
        Qs[i] = gq[i];
        Vs[i] = gv[i];
        KT[(i & 63) * 52 + (i >> 6)] = gk[i];
    }
    __syncthreads();

    // S = Q K^T * 0.125 + bias ; tasks: 49 rows x 13 j-blocks of 4
    for (int task = tid; task < NTOK * 13; task += 256) {
        int i = task / 13;
        int j0 = (task % 13) * 4;
        float a[4] = {0.f, 0.f, 0.f, 0.f};
        #pragma unroll
        for (int d = 0; d < 64; d++) {
            float qval = Qs[i * 64 + d];
            const float* kr = &KT[d * 52 + j0];
            a[0] += qval * kr[0];
            a[1] += qval * kr[1];
            a[2] += qval * kr[2];
            a[3] += qval * kr[3];
        }
        int ri = i / WS, ci = i % WS;
        #pragma unroll
        for (int c = 0; c < 4; c++) {
            int j = j0 + c;
            if (j < NTOK) {
                int rj = j / WS, cj = j % WS;
                int rel = (rj - ri + WS - 1) * (2 * WS - 1) + (cj - ci + WS - 1);
                float bias = __ldg(&pos_emb[rel * HEADS + h]);
                Ss[i * 50 + j] = a[c] * 0.125f + bias;
            }
        }
    }
    __syncthreads();

    // per-row softmax (49 rows handled by threads 0..48)
    if (tid < NTOK) {
        float* row = &Ss[tid * 50];
        float m = row[0];
        #pragma unroll
        for (int j = 1; j < NTOK; j++) m = fmaxf(m, row[j]);
        float s = 0.f;
        #pragma unroll
        for (int j = 0; j < NTOK; j++) {
            float e = expf(row[j] - m);
            row[j] = e;
            s += e;
        }
        float inv = 1.f / s;
        #pragma unroll
        for (int j = 0; j < NTOK; j++) row[j] *= inv;
    }
    __syncthreads();

    // O = P V ; store to g_a[b][h*64+d][w*49+i] (i fastest for coalescing)
    float* ga = g_a + ((long)b * INNER + h * 64) * NPIX + (long)w * NTOK;
    for (int e = tid; e < NTOK * 64; e += 256) {
        int i = e % NTOK, d = e / NTOK;
        float accum = 0.f;
        #pragma unroll
        for (int j = 0; j < NTOK; j++)
            accum += Ss[i * 50 + j] * Vs[j * 64 + d];
        ga[(long)d * NPIX + i] = accum;
    }
}

// ---------------------------------------------------------------------------
// Kernel 4: out-projection 512->256 SGEMM + bias, un-window on store
// grid: (25, 2, 16)
// ---------------------------------------------------------------------------
__global__ __launch_bounds__(256) void gemm_out_kernel(
    const float* __restrict__ Wo, const float* __restrict__ ob,
    float* __restrict__ out)
{
    __shared__ float As[8][128];
    __shared__ float Bs[8][128];

    int b = blockIdx.z;
    const float* A = Wo;  // [256,512]
    const float* B = g_a + (long)b * INNER * NPIX;

    int m0 = blockIdx.y * 128;
    int n0 = blockIdx.x * 128;
    int tid = threadIdx.x;
    int tx = tid & 15, ty = tid >> 4;
    int arow = tid >> 1, acol = (tid & 1) * 4;
    int brow = tid >> 5, bcol = (tid & 31) * 4;

    float acc[8][8];
    #pragma unroll
    for (int i = 0; i < 8; i++)
        #pragma unroll
        for (int j = 0; j < 8; j++) acc[i][j] = 0.f;

    const int K = INNER;
    for (int k0 = 0; k0 < K; k0 += 8) {
        float4 a4 = *(const float4*)&A[(long)(m0 + arow) * K + k0 + acol];
        As[acol + 0][arow] = a4.x;
        As[acol + 1][arow] = a4.y;
        As[acol + 2][arow] = a4.z;
        As[acol + 3][arow] = a4.w;
        float4 b4 = make_float4(0.f, 0.f, 0.f, 0.f);
        int n = n0 + bcol;
        if (n < NPIX) b4 = *(const float4*)&B[(long)(k0 + brow) * NPIX + n];
        *(float4*)&Bs[brow][bcol] = b4;
        __syncthreads();

        #pragma unroll
        for (int kk = 0; kk < 8; kk++) {
            float ar[8], br[8];
            *(float4*)(ar)     = *(float4*)&As[kk][ty * 8];
            *(float4*)(ar + 4) = *(float4*)&As[kk][ty * 8 + 4];
            *(float4*)(br)     = *(float4*)&Bs[kk][tx * 8];
            *(float4*)(br + 4) = *(float4*)&Bs[kk][tx * 8 + 4];
            #pragma unroll
            for (int i = 0; i < 8; i++)
                #pragma unroll
                for (int j = 0; j < 8; j++)
                    acc[i][j] += ar[i] * br[j];
        }
        __syncthreads();
    }

    #pragma unroll
    for (int mi = 0; mi < 8; mi++) {
        int o = m0 + ty * 8 + mi;
        float bias = __ldg(&ob[o]);
        #pragma unroll
        for (int ni = 0; ni < 8; ni++) {
            int p = n0 + tx * 8 + ni;    // windowed pixel index w*49+t
            if (p < NPIX) {
                int w = p / NTOK, t = p % NTOK;
                int yy = (w / 8) * WS + t / WS;
                int xx = (w % 8) * WS + t % WS;
                out[((long)b * DIMC + o) * NPIX + yy * HW + xx] = acc[mi][ni] + bias;
            }
        }
    }
}

// ---------------------------------------------------------------------------
extern "C" void kernel_launch(void* const* d_in, const int* in_sizes, int n_in,
                              void* d_out, int out_size)
{
    const float* x    = (const float*)d_in[0];
    const float* qdw  = (const float*)d_in[1];
    const float* qg   = (const float*)d_in[2];
    const float* qb   = (const float*)d_in[3];
    const float* qm   = (const float*)d_in[4];
    const float* qv   = (const float*)d_in[5];
    const float* qpw  = (const float*)d_in[6];
    const float* kdw  = (const float*)d_in[7];
    const float* kg   = (const float*)d_in[8];
    const float* kb   = (const float*)d_in[9];
    const float* km   = (const float*)d_in[10];
    const float* kv   = (const float*)d_in[11];
    const float* kpw  = (const float*)d_in[12];
    const float* vdw  = (const float*)d_in[13];
    const float* vg   = (const float*)d_in[14];
    const float* vb   = (const float*)d_in[15];
    const float* vm   = (const float*)d_in[16];
    const float* vv   = (const float*)d_in[17];
    const float* vpw  = (const float*)d_in[18];
    const float* pos  = (const float*)d_in[19];
    const float* outw = (const float*)d_in[20];
    const float* outb = (const float*)d_in[21];
    float* out = (float*)d_out;

    int total = BATCH * DIMC * NPIX;
    dwbn_kernel<<<(total + 255) / 256, 256>>>(x,
        qdw, qg, qb, qm, qv,
        kdw, kg, kb, km, kv,
        vdw, vg, vb, vm, vv);

    gemm_qkv_kernel<<<dim3(25, 4, 48), 256>>>(qpw, kpw, vpw);

    attn_kernel<<<dim3(NWIN, HEADS, BATCH), 256>>>(pos);

    gemm_out_kernel<<<dim3(25, 2, 16), 256>>>(outw, outb, out);
}

// round 3
// speedup vs baseline: 1.7838x; 1.7838x over previous
#include <cuda_runtime.h>
#include <cuda_bf16.h>
#include <cstdint>

#define DIMC   256
#define INNER  512
#define HEADS  8
#define DHEAD  64
#define WS     7
#define NTOK   49
#define HW     56
#define NPIX   3136      // 56*56, also 49*64
#define BATCH  16
#define NWIN   64        // 8*8 windows

// padded smem strides (words) — chosen to avoid STS bank pathologies
#define AS_KS_STRIDE 1060   // 8 matoms * 132 + 4 pad
#define AS_MA_STRIDE 132    // 32 lanes * 4 regs + 4 pad
#define BS_KS_STRIDE 1058   // 16 natoms * 66 + 2 pad
#define BS_NA_STRIDE 66     // 32 lanes * 2 regs + 2 pad
#define AS_WORDS (4 * AS_KS_STRIDE)
#define BS_WORDS (4 * BS_KS_STRIDE)

// ---------------- scratch (device globals; no allocation allowed) ----------
__device__ __align__(128) float g_y[3L * BATCH * DIMC * NPIX];   // dw+bn out [proj][b][c][p]
__device__ __align__(128) float g_qkv[3L * BATCH * INNER * NPIX];// [proj][b][h][w][t*64+d]
__device__ __align__(128) float g_a[(long)BATCH * INNER * NPIX]; // [b][h*64+d][w*49+t]

// ---------------------------------------------------------------------------
__device__ __forceinline__ uint32_t f2tf32(float x) {
    uint32_t r;
    asm("cvt.rna.tf32.f32 %0, %1;" : "=r"(r) : "f"(x));
    return r;
}

__device__ __forceinline__ void mma_tf32(float4& d, const uint32_t a[4],
                                         const uint32_t b[2], const float4& c) {
    asm volatile(
        "mma.sync.aligned.m16n8k8.row.col.f32.tf32.tf32.f32 "
        "{%0,%1,%2,%3}, {%4,%5,%6,%7}, {%8,%9}, {%10,%11,%12,%13};\n"
        : "=f"(d.x), "=f"(d.y), "=f"(d.z), "=f"(d.w)
        : "r"(a[0]), "r"(a[1]), "r"(a[2]), "r"(a[3]),
          "r"(b[0]), "r"(b[1]),
          "f"(c.x), "f"(c.y), "f"(c.z), "f"(c.w));
}

// Shared tf32 GEMM core: C[128x128] tile at (m0, n0) of A[*,K] x B[K,NPIX].
// acc[i][j] is warp-fragment accumulators (warp tile 64x32, atoms 16x8).
__device__ __forceinline__ void gemm_core(
    const float* __restrict__ A, const float* __restrict__ B,
    int K, int m0, int n0, uint32_t* As, uint32_t* Bs, float4 acc[4][4])
{
    const int tid = threadIdx.x;
    const int lane = tid & 31, warp = tid >> 5;
    const int wm = warp >> 2, wn = warp & 3;

    #pragma unroll
    for (int i = 0; i < 4; i++)
        #pragma unroll
        for (int j = 0; j < 4; j++) acc[i][j] = make_float4(0.f, 0.f, 0.f, 0.f);

    for (int k0 = 0; k0 < K; k0 += 32) {
        // ---- stage A tile 128x32 into fragment-permuted smem ----
        #pragma unroll
        for (int r = 0; r < 4; r++) {
            int idx = tid + r * 256;
            int m = idx >> 3;            // 0..127
            int kq = (idx & 7) * 4;      // 0,4,...,28
            float4 v = *(const float4*)&A[(m0 + m) * K + k0 + kq];
            int ks = kq >> 3, kh = (kq >> 2) & 1;
            int reg = ((m >> 3) & 1) | (kh << 1);
            int base = ks * AS_KS_STRIDE + (m >> 4) * AS_MA_STRIDE + reg;
            int lf = (m & 7) * 4;
            As[base + (lf + 0) * 4] = f2tf32(v.x);
            As[base + (lf + 1) * 4] = f2tf32(v.y);
            As[base + (lf + 2) * 4] = f2tf32(v.z);
            As[base + (lf + 3) * 4] = f2tf32(v.w);
        }
        // ---- stage B tile 32x128 ----
        #pragma unroll
        for (int r = 0; r < 4; r++) {
            int idx = tid + r * 256;
            int k = idx >> 5;            // 0..31
            int nq = (idx & 31) * 4;     // 0..124
            float4 v = make_float4(0.f, 0.f, 0.f, 0.f);
            if (n0 + nq < NPIX)
                v = *(const float4*)&B[(k0 + k) * NPIX + n0 + nq];
            int ks = k >> 3, kh = (k >> 2) & 1, k3 = k & 3;
            int base = ks * BS_KS_STRIDE + kh;
            int na0 = (nq >> 3);
            // nq%8 is 0 or 4; all 4 elems share natom
            int lf = ((nq & 7)) * 4 + k3;
            Bs[base + na0 * BS_NA_STRIDE + (lf + 0) * 2] = f2tf32(v.x);
            Bs[base + na0 * BS_NA_STRIDE + (lf + 4) * 2] = f2tf32(v.y);
            Bs[base + na0 * BS_NA_STRIDE + (lf + 8) * 2] = f2tf32(v.z);
            Bs[base + na0 * BS_NA_STRIDE + (lf + 12) * 2] = f2tf32(v.w);
        }
        __syncthreads();

        #pragma unroll
        for (int ks = 0; ks < 4; ks++) {
            uint32_t af[4][4];
            #pragma unroll
            for (int i = 0; i < 4; i++) {
                const uint4* p = (const uint4*)&As[ks * AS_KS_STRIDE +
                                                  (wm * 4 + i) * AS_MA_STRIDE + lane * 4];
                uint4 t = *p;
                af[i][0] = t.x; af[i][1] = t.y; af[i][2] = t.z; af[i][3] = t.w;
            }
            uint32_t bf[4][2];
            #pragma unroll
            for (int j = 0; j < 4; j++) {
                const uint2* p = (const uint2*)&Bs[ks * BS_KS_STRIDE +
                                                  (wn * 4 + j) * BS_NA_STRIDE + lane * 2];
                uint2 t = *p;
                bf[j][0] = t.x; bf[j][1] = t.y;
            }
            #pragma unroll
            for (int i = 0; i < 4; i++)
                #pragma unroll
                for (int j = 0; j < 4; j++)
                    mma_tf32(acc[i][j], af[i], bf[j], acc[i][j]);
        }
        __syncthreads();
    }
}

// ---------------------------------------------------------------------------
// Kernel 1: depthwise 3x3 conv + BN for q,k,v in one pass over x
// ---------------------------------------------------------------------------
__global__ void dwbn_kernel(const float* __restrict__ x,
    const float* __restrict__ qdw, const float* __restrict__ qg,
    const float* __restrict__ qb,  const float* __restrict__ qm,
    const float* __restrict__ qv,
    const float* __restrict__ kdw, const float* __restrict__ kg,
    const float* __restrict__ kb,  const float* __restrict__ km,
    const float* __restrict__ kv,
    const float* __restrict__ vdw, const float* __restrict__ vg,
    const float* __restrict__ vb,  const float* __restrict__ vm,
    const float* __restrict__ vv)
{
    int idx = blockIdx.x * blockDim.x + threadIdx.x;
    if (idx >= BATCH * DIMC * NPIX) return;
    int p = idx % NPIX;
    int c = (idx / NPIX) % DIMC;
    int b = idx / (NPIX * DIMC);
    int yy = p / HW, xx = p % HW;

    const float* xb = x + ((long)(b * DIMC + c)) * NPIX;
    float aq = 0.f, ak = 0.f, av = 0.f;
    #pragma unroll
    for (int ky = 0; ky < 3; ky++) {
        int iy = yy + ky - 1;
        if (iy < 0 || iy >= HW) continue;
        #pragma unroll
        for (int kx = 0; kx < 3; kx++) {
            int ix = xx + kx - 1;
            if (ix < 0 || ix >= HW) continue;
            float xval = xb[iy * HW + ix];
            int wi = c * 9 + ky * 3 + kx;
            aq += xval * __ldg(&qdw[wi]);
            ak += xval * __ldg(&kdw[wi]);
            av += xval * __ldg(&vdw[wi]);
        }
    }
    float sq = __ldg(&qg[c]) * rsqrtf(__ldg(&qv[c]) + 1e-5f);
    float sk = __ldg(&kg[c]) * rsqrtf(__ldg(&kv[c]) + 1e-5f);
    float sv = __ldg(&vg[c]) * rsqrtf(__ldg(&vv[c]) + 1e-5f);
    float oq = (aq - __ldg(&qm[c])) * sq + __ldg(&qb[c]);
    float ok = (ak - __ldg(&km[c])) * sk + __ldg(&kb[c]);
    float ov = (av - __ldg(&vm[c])) * sv + __ldg(&vb[c]);

    long base = ((long)b * DIMC + c) * NPIX + p;
    const long pstride = (long)BATCH * DIMC * NPIX;
    g_y[base]               = oq;
    g_y[base + pstride]     = ok;
    g_y[base + 2 * pstride] = ov;
}

// ---------------------------------------------------------------------------
// Kernel 2: qkv pointwise conv 256->512 as tf32 tensor-core GEMM.
// grid: (25, 4, 48);  windowed scatter-store on epilogue.
// ---------------------------------------------------------------------------
__global__ __launch_bounds__(256) void gemm_qkv_kernel(
    const float* __restrict__ pwq, const float* __restrict__ pwk,
    const float* __restrict__ pwv)
{
    __shared__ __align__(16) uint32_t As[AS_WORDS];
    __shared__ __align__(16) uint32_t Bs[BS_WORDS];

    int z = blockIdx.z;
    int proj = z >> 4;
    int b = z & 15;
    const float* A = (proj == 0) ? pwq : (proj == 1) ? pwk : pwv; // [512,256]
    const float* B = g_y + ((long)proj * BATCH + b) * DIMC * NPIX;

    int m0 = blockIdx.y * 128;
    int n0 = blockIdx.x * 128;

    float4 acc[4][4];
    gemm_core(A, B, DIMC, m0, n0, As, Bs, acc);

    const int lane = threadIdx.x & 31, warp = threadIdx.x >> 5;
    const int wm = warp >> 2, wn = warp & 3;
    const int gid = lane >> 2, tig = lane & 3;
    float* dst = g_qkv + ((long)proj * BATCH + b) * HEADS * NWIN * NPIX;

    #pragma unroll
    for (int i = 0; i < 4; i++) {
        int o_lo = m0 + wm * 64 + i * 16 + gid;
        int o_hi = o_lo + 8;
        #pragma unroll
        for (int j = 0; j < 4; j++) {
            int p0 = n0 + wn * 32 + j * 8 + tig * 2;
            int p1 = p0 + 1;
            float vals[4] = {acc[i][j].x, acc[i][j].y, acc[i][j].z, acc[i][j].w};
            int os[4] = {o_lo, o_lo, o_hi, o_hi};
            int ps[4] = {p0, p1, p0, p1};
            #pragma unroll
            for (int e = 0; e < 4; e++) {
                int p = ps[e];
                if (p < NPIX) {
                    int o = os[e];
                    int h = o >> 6, dd = o & 63;
                    int yy = p / HW, xx = p % HW;
                    int w = (yy / WS) * 8 + (xx / WS);
                    int t = (yy % WS) * WS + (xx % WS);
                    dst[((long)(h * NWIN + w)) * NPIX + t * 64 + dd] = vals[e];
                }
            }
        }
    }
}

// ---------------------------------------------------------------------------
// Kernel 3: windowed attention. one CTA per (b,h,w). 256 threads.
// ---------------------------------------------------------------------------
__global__ __launch_bounds__(256) void attn_kernel(const float* __restrict__ pos_emb)
{
    __shared__ float Qs[NTOK * 64];
    __shared__ float KT[64 * 52];
    __shared__ float Vs[NTOK * 64];
    __shared__ float Ss[NTOK * 50];

    int w = blockIdx.x, h = blockIdx.y, b = blockIdx.z;
    int tid = threadIdx.x;
    const long pstride = (long)BATCH * INNER * NPIX;
    long base = (((long)b * HEADS + h) * NWIN + w) * NPIX;
    const float* gq = g_qkv + base;
    const float* gk = g_qkv + base + pstride;
    const float* gv = g_qkv + base + 2 * pstride;

    for (int i = tid; i < NTOK * 64; i += 256) {
        Qs[i] = gq[i];
        Vs[i] = gv[i];
        KT[(i & 63) * 52 + (i >> 6)] = gk[i];
    }
    __syncthreads();

    for (int task = tid; task < NTOK * 13; task += 256) {
        int i = task / 13;
        int j0 = (task % 13) * 4;
        float a[4] = {0.f, 0.f, 0.f, 0.f};
        #pragma unroll
        for (int d = 0; d < 64; d++) {
            float qval = Qs[i * 64 + d];
            const float* kr = &KT[d * 52 + j0];
            a[0] += qval * kr[0];
            a[1] += qval * kr[1];
            a[2] += qval * kr[2];
            a[3] += qval * kr[3];
        }
        int ri = i / WS, ci = i % WS;
        #pragma unroll
        for (int c = 0; c < 4; c++) {
            int j = j0 + c;
            if (j < NTOK) {
                int rj = j / WS, cj = j % WS;
                int rel = (rj - ri + WS - 1) * (2 * WS - 1) + (cj - ci + WS - 1);
                float bias = __ldg(&pos_emb[rel * HEADS + h]);
                Ss[i * 50 + j] = a[c] * 0.125f + bias;
            }
        }
    }
    __syncthreads();

    if (tid < NTOK) {
        float* row = &Ss[tid * 50];
        float m = row[0];
        #pragma unroll
        for (int j = 1; j < NTOK; j++) m = fmaxf(m, row[j]);
        float s = 0.f;
        #pragma unroll
        for (int j = 0; j < NTOK; j++) {
            float e = expf(row[j] - m);
            row[j] = e;
            s += e;
        }
        float inv = 1.f / s;
        #pragma unroll
        for (int j = 0; j < NTOK; j++) row[j] *= inv;
    }
    __syncthreads();

    float* ga = g_a + ((long)b * INNER + h * 64) * NPIX + (long)w * NTOK;
    for (int e = tid; e < NTOK * 64; e += 256) {
        int i = e % NTOK, d = e / NTOK;
        float accum = 0.f;
        #pragma unroll
        for (int j = 0; j < NTOK; j++)
            accum += Ss[i * 50 + j] * Vs[j * 64 + d];
        ga[(long)d * NPIX + i] = accum;
    }
}

// ---------------------------------------------------------------------------
// Kernel 4: out-projection 512->256 tf32 GEMM + bias, un-window on store
// grid: (25, 2, 16)
// ---------------------------------------------------------------------------
__global__ __launch_bounds__(256) void gemm_out_kernel(
    const float* __restrict__ Wo, const float* __restrict__ ob,
    float* __restrict__ out)
{
    __shared__ __align__(16) uint32_t As[AS_WORDS];
    __shared__ __align__(16) uint32_t Bs[BS_WORDS];

    int b = blockIdx.z;
    const float* B = g_a + (long)b * INNER * NPIX;

    int m0 = blockIdx.y * 128;
    int n0 = blockIdx.x * 128;

    float4 acc[4][4];
    gemm_core(Wo, B, INNER, m0, n0, As, Bs, acc);

    const int lane = threadIdx.x & 31, warp = threadIdx.x >> 5;
    const int wm = warp >> 2, wn = warp & 3;
    const int gid = lane >> 2, tig = lane & 3;

    #pragma unroll
    for (int i = 0; i < 4; i++) {
        int o_lo = m0 + wm * 64 + i * 16 + gid;
        int o_hi = o_lo + 8;
        float bias_lo = __ldg(&ob[o_lo]);
        float bias_hi = __ldg(&ob[o_hi]);
        #pragma unroll
        for (int j = 0; j < 4; j++) {
            int p0 = n0 + wn * 32 + j * 8 + tig * 2;
            int p1 = p0 + 1;
            float vals[4] = {acc[i][j].x + bias_lo, acc[i][j].y + bias_lo,
                             acc[i][j].z + bias_hi, acc[i][j].w + bias_hi};
            int os[4] = {o_lo, o_lo, o_hi, o_hi};
            int ps[4] = {p0, p1, p0, p1};
            #pragma unroll
            for (int e = 0; e < 4; e++) {
                int p = ps[e];
                if (p < NPIX) {
                    int o = os[e];
                    int w = p / NTOK, t = p % NTOK;
                    int yy = (w / 8) * WS + t / WS;
                    int xx = (w % 8) * WS + t % WS;
                    out[((long)b * DIMC + o) * NPIX + yy * HW + xx] = vals[e];
                }
            }
        }
    }
}

// ---------------------------------------------------------------------------
extern "C" void kernel_launch(void* const* d_in, const int* in_sizes, int n_in,
                              void* d_out, int out_size)
{
    const float* x    = (const float*)d_in[0];
    const float* qdw  = (const float*)d_in[1];
    const float* qg   = (const float*)d_in[2];
    const float* qb   = (const float*)d_in[3];
    const float* qm   = (const float*)d_in[4];
    const float* qv   = (const float*)d_in[5];
    const float* qpw  = (const float*)d_in[6];
    const float* kdw  = (const float*)d_in[7];
    const float* kg   = (const float*)d_in[8];
    const float* kb   = (const float*)d_in[9];
    const float* km   = (const float*)d_in[10];
    const float* kv   = (const float*)d_in[11];
    const float* kpw  = (const float*)d_in[12];
    const float* vdw  = (const float*)d_in[13];
    const float* vg   = (const float*)d_in[14];
    const float* vb   = (const float*)d_in[15];
    const float* vm   = (const float*)d_in[16];
    const float* vv   = (const float*)d_in[17];
    const float* vpw  = (const float*)d_in[18];
    const float* pos  = (const float*)d_in[19];
    const float* outw = (const float*)d_in[20];
    const float* outb = (const float*)d_in[21];
    float* out = (float*)d_out;

    int total = BATCH * DIMC * NPIX;
    dwbn_kernel<<<(total + 255) / 256, 256>>>(x,
        qdw, qg, qb, qm, qv,
        kdw, kg, kb, km, kv,
        vdw, vg, vb, vm, vv);

    gemm_qkv_kernel<<<dim3(25, 4, 48), 256>>>(qpw, kpw, vpw);

    attn_kernel<<<dim3(NWIN, HEADS, BATCH), 256>>>(pos);

    gemm_out_kernel<<<dim3(25, 2, 16), 256>>>(outw, outb, out);
}

// round 4
// speedup vs baseline: 3.0483x; 1.7088x over previous
#include <cuda_runtime.h>
#include <cuda_bf16.h>
#include <cstdint>

#define DIMC   256
#define INNER  512
#define HEADS  8
#define DHEAD  64
#define WS     7
#define NTOK   49
#define HW     56
#define NPIX   3136      // 56*56, also 49*64
#define BATCH  16
#define NWIN   64        // 8*8 windows

// padded smem strides (words) — chosen to avoid STS bank pathologies
#define AS_KS_STRIDE 1060   // 8 matoms * 132 + 4 pad
#define AS_MA_STRIDE 132    // 32 lanes * 4 regs + 4 pad
#define BS_KS_STRIDE 1058   // 16 natoms * 66 + 2 pad
#define BS_NA_STRIDE 66     // 32 lanes * 2 regs + 2 pad
#define AS_WORDS (4 * AS_KS_STRIDE)
#define BS_WORDS (4 * BS_KS_STRIDE)

// attention smem strides (words)
#define QS_STR 68
#define KS_STR 68
#define VS_STR 72
#define PS_STR 60

// ---------------- scratch (device globals; no allocation allowed) ----------
__device__ __align__(128) float g_y[3L * BATCH * DIMC * NPIX];   // dw+bn out [proj][b][c][p]
__device__ __align__(128) float g_qkv[3L * BATCH * INNER * NPIX];// [proj][b][h][w][t*64+d]
__device__ __align__(128) float g_a[(long)BATCH * INNER * NPIX]; // [b][h*64+d][w*49+t]

// ---------------------------------------------------------------------------
__device__ __forceinline__ uint32_t f2tf32(float x) {
    uint32_t r;
    asm("cvt.rna.tf32.f32 %0, %1;" : "=r"(r) : "f"(x));
    return r;
}

__device__ __forceinline__ void mma_tf32(float4& d, const uint32_t a[4],
                                         const uint32_t b[2], const float4& c) {
    asm volatile(
        "mma.sync.aligned.m16n8k8.row.col.f32.tf32.tf32.f32 "
        "{%0,%1,%2,%3}, {%4,%5,%6,%7}, {%8,%9}, {%10,%11,%12,%13};\n"
        : "=f"(d.x), "=f"(d.y), "=f"(d.z), "=f"(d.w)
        : "r"(a[0]), "r"(a[1]), "r"(a[2]), "r"(a[3]),
          "r"(b[0]), "r"(b[1]),
          "f"(c.x), "f"(c.y), "f"(c.z), "f"(c.w));
}

// Shared tf32 GEMM core: C[128x128] tile at (m0, n0) of A[*,K] x B[K,NPIX].
__device__ __forceinline__ void gemm_core(
    const float* __restrict__ A, const float* __restrict__ B,
    int K, int m0, int n0, uint32_t* As, uint32_t* Bs, float4 acc[4][4])
{
    const int tid = threadIdx.x;
    const int lane = tid & 31, warp = tid >> 5;
    const int wm = warp >> 2, wn = warp & 3;

    #pragma unroll
    for (int i = 0; i < 4; i++)
        #pragma unroll
        for (int j = 0; j < 4; j++) acc[i][j] = make_float4(0.f, 0.f, 0.f, 0.f);

    for (int k0 = 0; k0 < K; k0 += 32) {
        #pragma unroll
        for (int r = 0; r < 4; r++) {
            int idx = tid + r * 256;
            int m = idx >> 3;
            int kq = (idx & 7) * 4;
            float4 v = *(const float4*)&A[(m0 + m) * K + k0 + kq];
            int ks = kq >> 3, kh = (kq >> 2) & 1;
            int reg = ((m >> 3) & 1) | (kh << 1);
            int base = ks * AS_KS_STRIDE + (m >> 4) * AS_MA_STRIDE + reg;
            int lf = (m & 7) * 4;
            As[base + (lf + 0) * 4] = f2tf32(v.x);
            As[base + (lf + 1) * 4] = f2tf32(v.y);
            As[base + (lf + 2) * 4] = f2tf32(v.z);
            As[base + (lf + 3) * 4] = f2tf32(v.w);
        }
        #pragma unroll
        for (int r = 0; r < 4; r++) {
            int idx = tid + r * 256;
            int k = idx >> 5;
            int nq = (idx & 31) * 4;
            float4 v = make_float4(0.f, 0.f, 0.f, 0.f);
            if (n0 + nq < NPIX)
                v = *(const float4*)&B[(k0 + k) * NPIX + n0 + nq];
            int ks = k >> 3, kh = (k >> 2) & 1, k3 = k & 3;
            int base = ks * BS_KS_STRIDE + kh;
            int na0 = (nq >> 3);
            int lf = ((nq & 7)) * 4 + k3;
            Bs[base + na0 * BS_NA_STRIDE + (lf + 0) * 2] = f2tf32(v.x);
            Bs[base + na0 * BS_NA_STRIDE + (lf + 4) * 2] = f2tf32(v.y);
            Bs[base + na0 * BS_NA_STRIDE + (lf + 8) * 2] = f2tf32(v.z);
            Bs[base + na0 * BS_NA_STRIDE + (lf + 12) * 2] = f2tf32(v.w);
        }
        __syncthreads();

        #pragma unroll
        for (int ks = 0; ks < 4; ks++) {
            uint32_t af[4][4];
            #pragma unroll
            for (int i = 0; i < 4; i++) {
                const uint4* p = (const uint4*)&As[ks * AS_KS_STRIDE +
                                                  (wm * 4 + i) * AS_MA_STRIDE + lane * 4];
                uint4 t = *p;
                af[i][0] = t.x; af[i][1] = t.y; af[i][2] = t.z; af[i][3] = t.w;
            }
            uint32_t bf[4][2];
            #pragma unroll
            for (int j = 0; j < 4; j++) {
                const uint2* p = (const uint2*)&Bs[ks * BS_KS_STRIDE +
                                                  (wn * 4 + j) * BS_NA_STRIDE + lane * 2];
                uint2 t = *p;
                bf[j][0] = t.x; bf[j][1] = t.y;
            }
            #pragma unroll
            for (int i = 0; i < 4; i++)
                #pragma unroll
                for (int j = 0; j < 4; j++)
                    mma_tf32(acc[i][j], af[i], bf[j], acc[i][j]);
        }
        __syncthreads();
    }
}

// ---------------------------------------------------------------------------
// Kernel 1: depthwise 3x3 conv + BN for q,k,v in one pass over x
// ---------------------------------------------------------------------------
__global__ void dwbn_kernel(const float* __restrict__ x,
    const float* __restrict__ qdw, const float* __restrict__ qg,
    const float* __restrict__ qb,  const float* __restrict__ qm,
    const float* __restrict__ qv,
    const float* __restrict__ kdw, const float* __restrict__ kg,
    const float* __restrict__ kb,  const float* __restrict__ km,
    const float* __restrict__ kv,
    const float* __restrict__ vdw, const float* __restrict__ vg,
    const float* __restrict__ vb,  const float* __restrict__ vm,
    const float* __restrict__ vv)
{
    int idx = blockIdx.x * blockDim.x + threadIdx.x;
    if (idx >= BATCH * DIMC * NPIX) return;
    int p = idx % NPIX;
    int c = (idx / NPIX) % DIMC;
    int b = idx / (NPIX * DIMC);
    int yy = p / HW, xx = p % HW;

    const float* xb = x + ((long)(b * DIMC + c)) * NPIX;
    float aq = 0.f, ak = 0.f, av = 0.f;
    #pragma unroll
    for (int ky = 0; ky < 3; ky++) {
        int iy = yy + ky - 1;
        if (iy < 0 || iy >= HW) continue;
        #pragma unroll
        for (int kx = 0; kx < 3; kx++) {
            int ix = xx + kx - 1;
            if (ix < 0 || ix >= HW) continue;
            float xval = xb[iy * HW + ix];
            int wi = c * 9 + ky * 3 + kx;
            aq += xval * __ldg(&qdw[wi]);
            ak += xval * __ldg(&kdw[wi]);
            av += xval * __ldg(&vdw[wi]);
        }
    }
    float sq = __ldg(&qg[c]) * rsqrtf(__ldg(&qv[c]) + 1e-5f);
    float sk = __ldg(&kg[c]) * rsqrtf(__ldg(&kv[c]) + 1e-5f);
    float sv = __ldg(&vg[c]) * rsqrtf(__ldg(&vv[c]) + 1e-5f);
    float oq = (aq - __ldg(&qm[c])) * sq + __ldg(&qb[c]);
    float ok = (ak - __ldg(&km[c])) * sk + __ldg(&kb[c]);
    float ov = (av - __ldg(&vm[c])) * sv + __ldg(&vb[c]);

    long base = ((long)b * DIMC + c) * NPIX + p;
    const long pstride = (long)BATCH * DIMC * NPIX;
    g_y[base]               = oq;
    g_y[base + pstride]     = ok;
    g_y[base + 2 * pstride] = ov;
}

// ---------------------------------------------------------------------------
// Kernel 2: qkv pointwise conv 256->512 as tf32 tensor-core GEMM.
// ---------------------------------------------------------------------------
__global__ __launch_bounds__(256) void gemm_qkv_kernel(
    const float* __restrict__ pwq, const float* __restrict__ pwk,
    const float* __restrict__ pwv)
{
    __shared__ __align__(16) uint32_t As[AS_WORDS];
    __shared__ __align__(16) uint32_t Bs[BS_WORDS];

    int z = blockIdx.z;
    int proj = z >> 4;
    int b = z & 15;
    const float* A = (proj == 0) ? pwq : (proj == 1) ? pwk : pwv; // [512,256]
    const float* B = g_y + ((long)proj * BATCH + b) * DIMC * NPIX;

    int m0 = blockIdx.y * 128;
    int n0 = blockIdx.x * 128;

    float4 acc[4][4];
    gemm_core(A, B, DIMC, m0, n0, As, Bs, acc);

    const int lane = threadIdx.x & 31, warp = threadIdx.x >> 5;
    const int wm = warp >> 2, wn = warp & 3;
    const int gid = lane >> 2, tig = lane & 3;
    float* dst = g_qkv + ((long)proj * BATCH + b) * HEADS * NWIN * NPIX;

    #pragma unroll
    for (int i = 0; i < 4; i++) {
        int o_lo = m0 + wm * 64 + i * 16 + gid;
        int o_hi = o_lo + 8;
        #pragma unroll
        for (int j = 0; j < 4; j++) {
            int p0 = n0 + wn * 32 + j * 8 + tig * 2;
            int p1 = p0 + 1;
            float vals[4] = {acc[i][j].x, acc[i][j].y, acc[i][j].z, acc[i][j].w};
            int os[4] = {o_lo, o_lo, o_hi, o_hi};
            int ps[4] = {p0, p1, p0, p1};
            #pragma unroll
            for (int e = 0; e < 4; e++) {
                int p = ps[e];
                if (p < NPIX) {
                    int o = os[e];
                    int h = o >> 6, dd = o & 63;
                    int yy = p / HW, xx = p % HW;
                    int w = (yy / WS) * 8 + (xx / WS);
                    int t = (yy % WS) * WS + (xx % WS);
                    dst[((long)(h * NWIN + w)) * NPIX + t * 64 + dd] = vals[e];
                }
            }
        }
    }
}

// ---------------------------------------------------------------------------
// Kernel 3: windowed attention on tensor cores. one CTA per (b,h,w).
// 128 threads = 4 warps; warp w owns output rows [16w, 16w+16).
// ---------------------------------------------------------------------------
__global__ __launch_bounds__(128) void attn_kernel(const float* __restrict__ pos_emb)
{
    __shared__ __align__(16) uint32_t Qs[64 * QS_STR];   // aliased as Ps in phase 2
    __shared__ __align__(16) uint32_t Ks[56 * KS_STR];
    __shared__ __align__(16) uint32_t Vs[56 * VS_STR];
    uint32_t* Ps = Qs;  // P[64 rows][56 cols], stride PS_STR (fits: 64*60 < 64*68)

    int w = blockIdx.x, h = blockIdx.y, b = blockIdx.z;
    int tid = threadIdx.x;
    int lane = tid & 31, warp = tid >> 5;
    int gi = lane >> 2, li = lane & 3;

    const long pstride = (long)BATCH * INNER * NPIX;
    long base = (((long)b * HEADS + h) * NWIN + w) * NPIX;
    const float* gq = g_qkv + base;
    const float* gk = g_qkv + base + pstride;
    const float* gv = g_qkv + base + 2 * pstride;

    // stage Q/K/V (tf32-converted); zero K/V pad rows 49..55
    for (int i = tid; i < NTOK * 64; i += 128) {
        int t = i >> 6, d = i & 63;
        Qs[t * QS_STR + d] = f2tf32(gq[i]);
        Ks[t * KS_STR + d] = f2tf32(gk[i]);
        Vs[t * VS_STR + d] = f2tf32(gv[i]);
    }
    for (int i = tid; i < 7 * 64; i += 128) {
        int t = NTOK + (i >> 6), d = i & 63;
        Ks[t * KS_STR + d] = 0;
        Vs[t * VS_STR + d] = 0;
    }
    __syncthreads();

    int row_lo = warp * 16 + gi;
    int row_hi = row_lo + 8;

    // ---- phase 1: S = Q K^T (M=64 pad, N=56 pad, K=64) ----
    uint32_t a[8][4];
    #pragma unroll
    for (int kk = 0; kk < 8; kk++) {
        a[kk][0] = Qs[row_lo * QS_STR + kk * 8 + li];
        a[kk][1] = Qs[row_hi * QS_STR + kk * 8 + li];
        a[kk][2] = Qs[row_lo * QS_STR + kk * 8 + li + 4];
        a[kk][3] = Qs[row_hi * QS_STR + kk * 8 + li + 4];
    }
    float4 c[7];
    #pragma unroll
    for (int j = 0; j < 7; j++) {
        c[j] = make_float4(0.f, 0.f, 0.f, 0.f);
        #pragma unroll
        for (int kk = 0; kk < 8; kk++) {
            uint32_t bf[2];
            bf[0] = Ks[(j * 8 + gi) * KS_STR + kk * 8 + li];
            bf[1] = Ks[(j * 8 + gi) * KS_STR + kk * 8 + li + 4];
            mma_tf32(c[j], a[kk], bf, c[j]);
        }
    }

    // ---- bias + softmax, all in registers (rows live in lane quads) ----
    int rr_lo = row_lo / 7, rc_lo = row_lo % 7;
    int rr_hi = row_hi / 7, rc_hi = row_hi % 7;
    float vlo[14], vhi[14];
    #pragma unroll
    for (int j = 0; j < 7; j++) {
        #pragma unroll
        for (int e = 0; e < 2; e++) {
            int col = j * 8 + li * 2 + e;
            float s_lo = (e == 0) ? c[j].x : c[j].y;
            float s_hi = (e == 0) ? c[j].z : c[j].w;
            if (col < NTOK) {
                int cr = col / 7, cc = col % 7;
                int rel_lo = (cr - rr_lo + 6) * 13 + (cc - rc_lo + 6);
                int rel_hi = (cr - rr_hi + 6) * 13 + (cc - rc_hi + 6);
                rel_lo = min(max(rel_lo, 0), 168);
                rel_hi = min(max(rel_hi, 0), 168);
                vlo[j * 2 + e] = fmaf(s_lo, 0.125f, __ldg(&pos_emb[rel_lo * HEADS + h]));
                vhi[j * 2 + e] = fmaf(s_hi, 0.125f, __ldg(&pos_emb[rel_hi * HEADS + h]));
            } else {
                vlo[j * 2 + e] = -1e30f;
                vhi[j * 2 + e] = -1e30f;
            }
        }
    }
    float mlo = -1e30f, mhi = -1e30f;
    #pragma unroll
    for (int i = 0; i < 14; i++) { mlo = fmaxf(mlo, vlo[i]); mhi = fmaxf(mhi, vhi[i]); }
    mlo = fmaxf(mlo, __shfl_xor_sync(0xffffffffu, mlo, 1));
    mlo = fmaxf(mlo, __shfl_xor_sync(0xffffffffu, mlo, 2));
    mhi = fmaxf(mhi, __shfl_xor_sync(0xffffffffu, mhi, 1));
    mhi = fmaxf(mhi, __shfl_xor_sync(0xffffffffu, mhi, 2));
    float slo = 0.f, shi = 0.f;
    #pragma unroll
    for (int i = 0; i < 14; i++) {
        vlo[i] = __expf(vlo[i] - mlo); slo += vlo[i];
        vhi[i] = __expf(vhi[i] - mhi); shi += vhi[i];
    }
    slo += __shfl_xor_sync(0xffffffffu, slo, 1);
    slo += __shfl_xor_sync(0xffffffffu, slo, 2);
    shi += __shfl_xor_sync(0xffffffffu, shi, 1);
    shi += __shfl_xor_sync(0xffffffffu, shi, 2);
    float ilo = 1.f / slo, ihi = 1.f / shi;

    __syncthreads();   // all Qs reads done everywhere before overwrite as Ps
    #pragma unroll
    for (int j = 0; j < 7; j++) {
        #pragma unroll
        for (int e = 0; e < 2; e++) {
            int col = j * 8 + li * 2 + e;
            Ps[row_lo * PS_STR + col] = f2tf32(vlo[j * 2 + e] * ilo);
            Ps[row_hi * PS_STR + col] = f2tf32(vhi[j * 2 + e] * ihi);
        }
    }
    __syncthreads();

    // ---- phase 2: O = P V (M=64 pad, N=64, K=56 pad) ----
    uint32_t pa[7][4];
    #pragma unroll
    for (int kk = 0; kk < 7; kk++) {
        pa[kk][0] = Ps[row_lo * PS_STR + kk * 8 + li];
        pa[kk][1] = Ps[row_hi * PS_STR + kk * 8 + li];
        pa[kk][2] = Ps[row_lo * PS_STR + kk * 8 + li + 4];
        pa[kk][3] = Ps[row_hi * PS_STR + kk * 8 + li + 4];
    }
    float* ga = g_a + ((long)b * INNER + h * 64) * NPIX + (long)w * NTOK;
    #pragma unroll
    for (int dn = 0; dn < 8; dn++) {
        float4 o = make_float4(0.f, 0.f, 0.f, 0.f);
        #pragma unroll
        for (int kk = 0; kk < 7; kk++) {
            uint32_t bf[2];
            bf[0] = Vs[(kk * 8 + li) * VS_STR + dn * 8 + gi];
            bf[1] = Vs[(kk * 8 + li + 4) * VS_STR + dn * 8 + gi];
            mma_tf32(o, pa[kk], bf, o);
        }
        int d0 = dn * 8 + li * 2;
        if (row_lo < NTOK) {
            ga[(long)d0 * NPIX + row_lo]       = o.x;
            ga[(long)(d0 + 1) * NPIX + row_lo] = o.y;
        }
        if (row_hi < NTOK) {
            ga[(long)d0 * NPIX + row_hi]       = o.z;
            ga[(long)(d0 + 1) * NPIX + row_hi] = o.w;
        }
    }
}

// ---------------------------------------------------------------------------
// Kernel 4: out-projection 512->256 tf32 GEMM + bias, un-window on store
// ---------------------------------------------------------------------------
__global__ __launch_bounds__(256) void gemm_out_kernel(
    const float* __restrict__ Wo, const float* __restrict__ ob,
    float* __restrict__ out)
{
    __shared__ __align__(16) uint32_t As[AS_WORDS];
    __shared__ __align__(16) uint32_t Bs[BS_WORDS];

    int b = blockIdx.z;
    const float* B = g_a + (long)b * INNER * NPIX;

    int m0 = blockIdx.y * 128;
    int n0 = blockIdx.x * 128;

    float4 acc[4][4];
    gemm_core(Wo, B, INNER, m0, n0, As, Bs, acc);

    const int lane = threadIdx.x & 31, warp = threadIdx.x >> 5;
    const int wm = warp >> 2, wn = warp & 3;
    const int gid = lane >> 2, tig = lane & 3;

    #pragma unroll
    for (int i = 0; i < 4; i++) {
        int o_lo = m0 + wm * 64 + i * 16 + gid;
        int o_hi = o_lo + 8;
        float bias_lo = __ldg(&ob[o_lo]);
        float bias_hi = __ldg(&ob[o_hi]);
        #pragma unroll
        for (int j = 0; j < 4; j++) {
            int p0 = n0 + wn * 32 + j * 8 + tig * 2;
            int p1 = p0 + 1;
            float vals[4] = {acc[i][j].x + bias_lo, acc[i][j].y + bias_lo,
                             acc[i][j].z + bias_hi, acc[i][j].w + bias_hi};
            int os[4] = {o_lo, o_lo, o_hi, o_hi};
            int ps[4] = {p0, p1, p0, p1};
            #pragma unroll
            for (int e = 0; e < 4; e++) {
                int p = ps[e];
                if (p < NPIX) {
                    int o = os[e];
                    int w = p / NTOK, t = p % NTOK;
                    int yy = (w / 8) * WS + t / WS;
                    int xx = (w % 8) * WS + t % WS;
                    out[((long)b * DIMC + o) * NPIX + yy * HW + xx] = vals[e];
                }
            }
        }
    }
}

// ---------------------------------------------------------------------------
extern "C" void kernel_launch(void* const* d_in, const int* in_sizes, int n_in,
                              void* d_out, int out_size)
{
    const float* x    = (const float*)d_in[0];
    const float* qdw  = (const float*)d_in[1];
    const float* qg   = (const float*)d_in[2];
    const float* qb   = (const float*)d_in[3];
    const float* qm   = (const float*)d_in[4];
    const float* qv   = (const float*)d_in[5];
    const float* qpw  = (const float*)d_in[6];
    const float* kdw  = (const float*)d_in[7];
    const float* kg   = (const float*)d_in[8];
    const float* kb   = (const float*)d_in[9];
    const float* km   = (const float*)d_in[10];
    const float* kv   = (const float*)d_in[11];
    const float* kpw  = (const float*)d_in[12];
    const float* vdw  = (const float*)d_in[13];
    const float* vg   = (const float*)d_in[14];
    const float* vb   = (const float*)d_in[15];
    const float* vm   = (const float*)d_in[16];
    const float* vv   = (const float*)d_in[17];
    const float* vpw  = (const float*)d_in[18];
    const float* pos  = (const float*)d_in[19];
    const float* outw = (const float*)d_in[20];
    const float* outb = (const float*)d_in[21];
    float* out = (float*)d_out;

    int total = BATCH * DIMC * NPIX;
    dwbn_kernel<<<(total + 255) / 256, 256>>>(x,
        qdw, qg, qb, qm, qv,
        kdw, kg, kb, km, kv,
        vdw, vg, vb, vm, vv);

    gemm_qkv_kernel<<<dim3(25, 4, 48), 256>>>(qpw, kpw, vpw);

    attn_kernel<<<dim3(NWIN, HEADS, BATCH), 128>>>(pos);

    gemm_out_kernel<<<dim3(25, 2, 16), 256>>>(outw, outb, out);
}

// round 5
// speedup vs baseline: 3.3156x; 1.0877x over previous
#include <cuda_runtime.h>
#include <cuda_bf16.h>
#include <cstdint>

#define DIMC   256
#define INNER  512
#define HEADS  8
#define DHEAD  64
#define WS     7
#define NTOK   49
#define HW     56
#define NPIX   3136      // 56*56, also 49*64
#define BATCH  16
#define NWIN   64        // 8*8 windows

// GEMM smem strides (words) — conflict-free fragment LDS (see analysis)
#define AST 36           // A tile row stride (32 data + 4 pad)
#define BST 136          // B tile row stride (128 data + 8 pad)
#define A_WORDS (128 * AST)   // 4608
#define B_WORDS (32 * BST)    // 4352
#define NSTAGE 3
#define GEMM_SMEM_BYTES ((NSTAGE * (A_WORDS + B_WORDS)) * 4)

// attention smem strides (words)
#define QS_STR 68
#define KS_STR 68
#define VS_STR 72
#define PS_STR 60

// ---------------- scratch (device globals; no allocation allowed) ----------
__device__ __align__(128) float g_y[3L * BATCH * DIMC * NPIX];   // dw+bn out (tf32-rounded)
__device__ __align__(128) float g_qkv[3L * BATCH * INNER * NPIX];// [proj][b][h][w][t*64+d]
__device__ __align__(128) float g_a[(long)BATCH * INNER * NPIX]; // attn out (tf32-rounded)
__device__ __align__(128) float g_w[4L * 131072];                // tf32-rounded weights

// ---------------------------------------------------------------------------
__device__ __forceinline__ uint32_t f2tf32(float x) {
    uint32_t r;
    asm("cvt.rna.tf32.f32 %0, %1;" : "=r"(r) : "f"(x));
    return r;
}

__device__ __forceinline__ void mma_tf32(float4& d, const uint32_t a[4],
                                         const uint32_t b[2], const float4& c) {
    asm volatile(
        "mma.sync.aligned.m16n8k8.row.col.f32.tf32.tf32.f32 "
        "{%0,%1,%2,%3}, {%4,%5,%6,%7}, {%8,%9}, {%10,%11,%12,%13};\n"
        : "=f"(d.x), "=f"(d.y), "=f"(d.z), "=f"(d.w)
        : "r"(a[0]), "r"(a[1]), "r"(a[2]), "r"(a[3]),
          "r"(b[0]), "r"(b[1]),
          "f"(c.x), "f"(c.y), "f"(c.z), "f"(c.w));
}

__device__ __forceinline__ void cpa16(uint32_t dst, const void* src) {
    asm volatile("cp.async.cg.shared.global [%0], [%1], 16;\n"
                 :: "r"(dst), "l"(src));
}
__device__ __forceinline__ void cpa16z(uint32_t dst, const void* src, bool ok) {
    int sz = ok ? 16 : 0;
    asm volatile("cp.async.cg.shared.global [%0], [%1], 16, %2;\n"
                 :: "r"(dst), "l"(src), "r"(sz));
}

// issue one k-tile stage (A 128x32, B 32x128) via cp.async + commit
__device__ __forceinline__ void gemm_stage(const float* __restrict__ A,
                                           const float* __restrict__ B,
                                           int K, int m0, int n0, int k0,
                                           uint32_t sa, uint32_t sb, int tid)
{
    #pragma unroll
    for (int r = 0; r < 4; r++) {
        int idx = tid + r * 256;
        int row = idx >> 3, cc = idx & 7;
        cpa16(sa + (row * AST + cc * 4) * 4,
              &A[(long)(m0 + row) * K + k0 + cc * 4]);
    }
    #pragma unroll
    for (int r = 0; r < 4; r++) {
        int idx = tid + r * 256;
        int row = idx >> 5, cc = idx & 31;
        int n = n0 + cc * 4;
        cpa16z(sb + (row * BST + cc * 4) * 4,
               &B[(long)(k0 + row) * NPIX + n], n < NPIX);
    }
    asm volatile("cp.async.commit_group;\n" ::: "memory");
}

// pipelined tf32 GEMM core: C[128x128] at (m0,n0) of A[*,K] x B[K,NPIX].
// smem: dynamic, values pre-rounded to tf32.
__device__ __forceinline__ void gemm_core(
    const float* __restrict__ A, const float* __restrict__ B,
    int K, int m0, int n0, float* smA, float* smB, float4 acc[4][4])
{
    const int tid = threadIdx.x;
    const int lane = tid & 31, warp = tid >> 5;
    const int wm = warp >> 2, wn = warp & 3;
    const int gi = lane >> 2, li = lane & 3;

    #pragma unroll
    for (int i = 0; i < 4; i++)
        #pragma unroll
        for (int j = 0; j < 4; j++) acc[i][j] = make_float4(0.f, 0.f, 0.f, 0.f);

    uint32_t saB = (uint32_t)__cvta_generic_to_shared(smA);
    uint32_t sbB = (uint32_t)__cvta_generic_to_shared(smB);

    const int nk = K >> 5;
    gemm_stage(A, B, K, m0, n0, 0, saB, sbB, tid);
    gemm_stage(A, B, K, m0, n0, 32, saB + A_WORDS * 4, sbB + B_WORDS * 4, tid);

    for (int kt = 0; kt < nk; kt++) {
        if (kt + 1 < nk)
            asm volatile("cp.async.wait_group 1;\n" ::: "memory");
        else
            asm volatile("cp.async.wait_group 0;\n" ::: "memory");
        __syncthreads();

        const float* As = smA + (kt % NSTAGE) * A_WORDS;
        const float* Bs = smB + (kt % NSTAGE) * B_WORDS;

        #pragma unroll
        for (int ks = 0; ks < 4; ks++) {
            uint32_t bf[4][2];
            #pragma unroll
            for (int j = 0; j < 4; j++) {
                int n = wn * 32 + j * 8 + gi;
                bf[j][0] = __float_as_uint(Bs[(ks * 8 + li) * BST + n]);
                bf[j][1] = __float_as_uint(Bs[(ks * 8 + li + 4) * BST + n]);
            }
            #pragma unroll
            for (int i = 0; i < 4; i++) {
                int rlo = wm * 64 + i * 16 + gi;
                uint32_t af[4];
                af[0] = __float_as_uint(As[rlo * AST + ks * 8 + li]);
                af[1] = __float_as_uint(As[(rlo + 8) * AST + ks * 8 + li]);
                af[2] = __float_as_uint(As[rlo * AST + ks * 8 + li + 4]);
                af[3] = __float_as_uint(As[(rlo + 8) * AST + ks * 8 + li + 4]);
                #pragma unroll
                for (int j = 0; j < 4; j++)
                    mma_tf32(acc[i][j], af, bf[j], acc[i][j]);
            }
        }

        if (kt + 2 < nk) {
            int s = (kt + 2) % NSTAGE;
            gemm_stage(A, B, K, m0, n0, (kt + 2) * 32,
                       saB + s * A_WORDS * 4, sbB + s * B_WORDS * 4, tid);
        }
    }
}

// ---------------------------------------------------------------------------
// Kernel 0: round all weights to tf32 once
// ---------------------------------------------------------------------------
__global__ void prep_w_kernel(const float* __restrict__ pwq,
                              const float* __restrict__ pwk,
                              const float* __restrict__ pwv,
                              const float* __restrict__ wo)
{
    int i = blockIdx.x * 256 + threadIdx.x;
    if (i >= 4 * 131072) return;
    float v;
    if (i < 131072)       v = pwq[i];
    else if (i < 262144)  v = pwk[i - 131072];
    else if (i < 393216)  v = pwv[i - 262144];
    else                  v = wo[i - 393216];
    g_w[i] = __uint_as_float(f2tf32(v));
}

// ---------------------------------------------------------------------------
// Kernel 1: depthwise 3x3 conv + BN for q,k,v; store tf32-rounded
// ---------------------------------------------------------------------------
__global__ void dwbn_kernel(const float* __restrict__ x,
    const float* __restrict__ qdw, const float* __restrict__ qg,
    const float* __restrict__ qb,  const float* __restrict__ qm,
    const float* __restrict__ qv,
    const float* __restrict__ kdw, const float* __restrict__ kg,
    const float* __restrict__ kb,  const float* __restrict__ km,
    const float* __restrict__ kv,
    const float* __restrict__ vdw, const float* __restrict__ vg,
    const float* __restrict__ vb,  const float* __restrict__ vm,
    const float* __restrict__ vv)
{
    int idx = blockIdx.x * blockDim.x + threadIdx.x;
    if (idx >= BATCH * DIMC * NPIX) return;
    int p = idx % NPIX;
    int c = (idx / NPIX) % DIMC;
    int b = idx / (NPIX * DIMC);
    int yy = p / HW, xx = p % HW;

    const float* xb = x + ((long)(b * DIMC + c)) * NPIX;
    float aq = 0.f, ak = 0.f, av = 0.f;
    #pragma unroll
    for (int ky = 0; ky < 3; ky++) {
        int iy = yy + ky - 1;
        if (iy < 0 || iy >= HW) continue;
        #pragma unroll
        for (int kx = 0; kx < 3; kx++) {
            int ix = xx + kx - 1;
            if (ix < 0 || ix >= HW) continue;
            float xval = xb[iy * HW + ix];
            int wi = c * 9 + ky * 3 + kx;
            aq += xval * __ldg(&qdw[wi]);
            ak += xval * __ldg(&kdw[wi]);
            av += xval * __ldg(&vdw[wi]);
        }
    }
    float sq = __ldg(&qg[c]) * rsqrtf(__ldg(&qv[c]) + 1e-5f);
    float sk = __ldg(&kg[c]) * rsqrtf(__ldg(&kv[c]) + 1e-5f);
    float sv = __ldg(&vg[c]) * rsqrtf(__ldg(&vv[c]) + 1e-5f);
    float oq = (aq - __ldg(&qm[c])) * sq + __ldg(&qb[c]);
    float ok = (ak - __ldg(&km[c])) * sk + __ldg(&kb[c]);
    float ov = (av - __ldg(&vm[c])) * sv + __ldg(&vb[c]);

    long base = ((long)b * DIMC + c) * NPIX + p;
    const long pstride = (long)BATCH * DIMC * NPIX;
    g_y[base]               = __uint_as_float(f2tf32(oq));
    g_y[base + pstride]     = __uint_as_float(f2tf32(ok));
    g_y[base + 2 * pstride] = __uint_as_float(f2tf32(ov));
}

// ---------------------------------------------------------------------------
// Kernel 2: qkv pointwise conv 256->512, pipelined tf32 GEMM.
// grid: (25, 4, 48)
// ---------------------------------------------------------------------------
__global__ __launch_bounds__(256) void gemm_qkv_kernel()
{
    extern __shared__ __align__(16) float smem[];
    float* smA = smem;
    float* smB = smem + NSTAGE * A_WORDS;

    int z = blockIdx.z;
    int proj = z >> 4;
    int b = z & 15;
    const float* A = g_w + (long)proj * 131072;          // [512,256] tf32
    const float* B = g_y + ((long)proj * BATCH + b) * DIMC * NPIX;

    int m0 = blockIdx.y * 128;
    int n0 = blockIdx.x * 128;

    float4 acc[4][4];
    gemm_core(A, B, DIMC, m0, n0, smA, smB, acc);

    const int lane = threadIdx.x & 31, warp = threadIdx.x >> 5;
    const int wm = warp >> 2, wn = warp & 3;
    const int gid = lane >> 2, tig = lane & 3;
    float* dst = g_qkv + ((long)proj * BATCH + b) * HEADS * NWIN * NPIX;

    #pragma unroll
    for (int i = 0; i < 4; i++) {
        int o_lo = m0 + wm * 64 + i * 16 + gid;
        int o_hi = o_lo + 8;
        #pragma unroll
        for (int j = 0; j < 4; j++) {
            int p0 = n0 + wn * 32 + j * 8 + tig * 2;
            int p1 = p0 + 1;
            float vals[4] = {acc[i][j].x, acc[i][j].y, acc[i][j].z, acc[i][j].w};
            int os[4] = {o_lo, o_lo, o_hi, o_hi};
            int ps[4] = {p0, p1, p0, p1};
            #pragma unroll
            for (int e = 0; e < 4; e++) {
                int p = ps[e];
                if (p < NPIX) {
                    int o = os[e];
                    int h = o >> 6, dd = o & 63;
                    int yy = p / HW, xx = p % HW;
                    int w = (yy / WS) * 8 + (xx / WS);
                    int t = (yy % WS) * WS + (xx % WS);
                    dst[((long)(h * NWIN + w)) * NPIX + t * 64 + dd] = vals[e];
                }
            }
        }
    }
}

// ---------------------------------------------------------------------------
// Kernel 3: windowed attention on tensor cores. one CTA per (b,h,w).
// ---------------------------------------------------------------------------
__global__ __launch_bounds__(128) void attn_kernel(const float* __restrict__ pos_emb)
{
    __shared__ __align__(16) uint32_t Qs[64 * QS_STR];   // aliased as Ps in phase 2
    __shared__ __align__(16) uint32_t Ks[56 * KS_STR];
    __shared__ __align__(16) uint32_t Vs[56 * VS_STR];
    uint32_t* Ps = Qs;

    int w = blockIdx.x, h = blockIdx.y, b = blockIdx.z;
    int tid = threadIdx.x;
    int lane = tid & 31, warp = tid >> 5;
    int gi = lane >> 2, li = lane & 3;

    const long pstride = (long)BATCH * INNER * NPIX;
    long base = (((long)b * HEADS + h) * NWIN + w) * NPIX;
    const float* gq = g_qkv + base;
    const float* gk = g_qkv + base + pstride;
    const float* gv = g_qkv + base + 2 * pstride;

    for (int i = tid; i < NTOK * 64; i += 128) {
        int t = i >> 6, d = i & 63;
        Qs[t * QS_STR + d] = f2tf32(gq[i]);
        Ks[t * KS_STR + d] = f2tf32(gk[i]);
        Vs[t * VS_STR + d] = f2tf32(gv[i]);
    }
    for (int i = tid; i < 7 * 64; i += 128) {
        int t = NTOK + (i >> 6), d = i & 63;
        Ks[t * KS_STR + d] = 0;
        Vs[t * VS_STR + d] = 0;
    }
    __syncthreads();

    int row_lo = warp * 16 + gi;
    int row_hi = row_lo + 8;

    // ---- phase 1: S = Q K^T ----
    uint32_t a[8][4];
    #pragma unroll
    for (int kk = 0; kk < 8; kk++) {
        a[kk][0] = Qs[row_lo * QS_STR + kk * 8 + li];
        a[kk][1] = Qs[row_hi * QS_STR + kk * 8 + li];
        a[kk][2] = Qs[row_lo * QS_STR + kk * 8 + li + 4];
        a[kk][3] = Qs[row_hi * QS_STR + kk * 8 + li + 4];
    }
    float4 c[7];
    #pragma unroll
    for (int j = 0; j < 7; j++) {
        c[j] = make_float4(0.f, 0.f, 0.f, 0.f);
        #pragma unroll
        for (int kk = 0; kk < 8; kk++) {
            uint32_t bf[2];
            bf[0] = Ks[(j * 8 + gi) * KS_STR + kk * 8 + li];
            bf[1] = Ks[(j * 8 + gi) * KS_STR + kk * 8 + li + 4];
            mma_tf32(c[j], a[kk], bf, c[j]);
        }
    }

    // ---- bias + softmax in registers ----
    int rr_lo = row_lo / 7, rc_lo = row_lo % 7;
    int rr_hi = row_hi / 7, rc_hi = row_hi % 7;
    float vlo[14], vhi[14];
    #pragma unroll
    for (int j = 0; j < 7; j++) {
        #pragma unroll
        for (int e = 0; e < 2; e++) {
            int col = j * 8 + li * 2 + e;
            float s_lo = (e == 0) ? c[j].x : c[j].y;
            float s_hi = (e == 0) ? c[j].z : c[j].w;
            if (col < NTOK) {
                int cr = col / 7, cc = col % 7;
                int rel_lo = (cr - rr_lo + 6) * 13 + (cc - rc_lo + 6);
                int rel_hi = (cr - rr_hi + 6) * 13 + (cc - rc_hi + 6);
                rel_lo = min(max(rel_lo, 0), 168);
                rel_hi = min(max(rel_hi, 0), 168);
                vlo[j * 2 + e] = fmaf(s_lo, 0.125f, __ldg(&pos_emb[rel_lo * HEADS + h]));
                vhi[j * 2 + e] = fmaf(s_hi, 0.125f, __ldg(&pos_emb[rel_hi * HEADS + h]));
            } else {
                vlo[j * 2 + e] = -1e30f;
                vhi[j * 2 + e] = -1e30f;
            }
        }
    }
    float mlo = -1e30f, mhi = -1e30f;
    #pragma unroll
    for (int i = 0; i < 14; i++) { mlo = fmaxf(mlo, vlo[i]); mhi = fmaxf(mhi, vhi[i]); }
    mlo = fmaxf(mlo, __shfl_xor_sync(0xffffffffu, mlo, 1));
    mlo = fmaxf(mlo, __shfl_xor_sync(0xffffffffu, mlo, 2));
    mhi = fmaxf(mhi, __shfl_xor_sync(0xffffffffu, mhi, 1));
    mhi = fmaxf(mhi, __shfl_xor_sync(0xffffffffu, mhi, 2));
    float slo = 0.f, shi = 0.f;
    #pragma unroll
    for (int i = 0; i < 14; i++) {
        vlo[i] = __expf(vlo[i] - mlo); slo += vlo[i];
        vhi[i] = __expf(vhi[i] - mhi); shi += vhi[i];
    }
    slo += __shfl_xor_sync(0xffffffffu, slo, 1);
    slo += __shfl_xor_sync(0xffffffffu, slo, 2);
    shi += __shfl_xor_sync(0xffffffffu, shi, 1);
    shi += __shfl_xor_sync(0xffffffffu, shi, 2);
    float ilo = 1.f / slo, ihi = 1.f / shi;

    __syncthreads();
    #pragma unroll
    for (int j = 0; j < 7; j++) {
        #pragma unroll
        for (int e = 0; e < 2; e++) {
            int col = j * 8 + li * 2 + e;
            Ps[row_lo * PS_STR + col] = f2tf32(vlo[j * 2 + e] * ilo);
            Ps[row_hi * PS_STR + col] = f2tf32(vhi[j * 2 + e] * ihi);
        }
    }
    __syncthreads();

    // ---- phase 2: O = P V ----
    uint32_t pa[7][4];
    #pragma unroll
    for (int kk = 0; kk < 7; kk++) {
        pa[kk][0] = Ps[row_lo * PS_STR + kk * 8 + li];
        pa[kk][1] = Ps[row_hi * PS_STR + kk * 8 + li];
        pa[kk][2] = Ps[row_lo * PS_STR + kk * 8 + li + 4];
        pa[kk][3] = Ps[row_hi * PS_STR + kk * 8 + li + 4];
    }
    float* ga = g_a + ((long)b * INNER + h * 64) * NPIX + (long)w * NTOK;
    #pragma unroll
    for (int dn = 0; dn < 8; dn++) {
        float4 o = make_float4(0.f, 0.f, 0.f, 0.f);
        #pragma unroll
        for (int kk = 0; kk < 7; kk++) {
            uint32_t bf[2];
            bf[0] = Vs[(kk * 8 + li) * VS_STR + dn * 8 + gi];
            bf[1] = Vs[(kk * 8 + li + 4) * VS_STR + dn * 8 + gi];
            mma_tf32(o, pa[kk], bf, o);
        }
        int d0 = dn * 8 + li * 2;
        if (row_lo < NTOK) {
            ga[(long)d0 * NPIX + row_lo]       = __uint_as_float(f2tf32(o.x));
            ga[(long)(d0 + 1) * NPIX + row_lo] = __uint_as_float(f2tf32(o.y));
        }
        if (row_hi < NTOK) {
            ga[(long)d0 * NPIX + row_hi]       = __uint_as_float(f2tf32(o.z));
            ga[(long)(d0 + 1) * NPIX + row_hi] = __uint_as_float(f2tf32(o.w));
        }
    }
}

// ---------------------------------------------------------------------------
// Kernel 4: out-projection 512->256 pipelined tf32 GEMM + bias, un-window
// grid: (25, 2, 16)
// ---------------------------------------------------------------------------
__global__ __launch_bounds__(256) void gemm_out_kernel(
    const float* __restrict__ ob, float* __restrict__ out)
{
    extern __shared__ __align__(16) float smem[];
    float* smA = smem;
    float* smB = smem + NSTAGE * A_WORDS;

    int b = blockIdx.z;
    const float* A = g_w + 3L * 131072;                  // [256,512] tf32
    const float* B = g_a + (long)b * INNER * NPIX;

    int m0 = blockIdx.y * 128;
    int n0 = blockIdx.x * 128;

    float4 acc[4][4];
    gemm_core(A, B, INNER, m0, n0, smA, smB, acc);

    const int lane = threadIdx.x & 31, warp = threadIdx.x >> 5;
    const int wm = warp >> 2, wn = warp & 3;
    const int gid = lane >> 2, tig = lane & 3;

    #pragma unroll
    for (int i = 0; i < 4; i++) {
        int o_lo = m0 + wm * 64 + i * 16 + gid;
        int o_hi = o_lo + 8;
        float bias_lo = __ldg(&ob[o_lo]);
        float bias_hi = __ldg(&ob[o_hi]);
        #pragma unroll
        for (int j = 0; j < 4; j++) {
            int p0 = n0 + wn * 32 + j * 8 + tig * 2;
            int p1 = p0 + 1;
            float vals[4] = {acc[i][j].x + bias_lo, acc[i][j].y + bias_lo,
                             acc[i][j].z + bias_hi, acc[i][j].w + bias_hi};
            int os[4] = {o_lo, o_lo, o_hi, o_hi};
            int ps[4] = {p0, p1, p0, p1};
            #pragma unroll
            for (int e = 0; e < 4; e++) {
                int p = ps[e];
                if (p < NPIX) {
                    int o = os[e];
                    int w = p / NTOK, t = p % NTOK;
                    int yy = (w / 8) * WS + t / WS;
                    int xx = (w % 8) * WS + t % WS;
                    out[((long)b * DIMC + o) * NPIX + yy * HW + xx] = vals[e];
                }
            }
        }
    }
}

// ---------------------------------------------------------------------------
extern "C" void kernel_launch(void* const* d_in, const int* in_sizes, int n_in,
                              void* d_out, int out_size)
{
    const float* x    = (const float*)d_in[0];
    const float* qdw  = (const float*)d_in[1];
    const float* qg   = (const float*)d_in[2];
    const float* qb   = (const float*)d_in[3];
    const float* qm   = (const float*)d_in[4];
    const float* qv   = (const float*)d_in[5];
    const float* qpw  = (const float*)d_in[6];
    const float* kdw  = (const float*)d_in[7];
    const float* kg   = (const float*)d_in[8];
    const float* kb   = (const float*)d_in[9];
    const float* km   = (const float*)d_in[10];
    const float* kv   = (const float*)d_in[11];
    const float* kpw  = (const float*)d_in[12];
    const float* vdw  = (const float*)d_in[13];
    const float* vg   = (const float*)d_in[14];
    const float* vb   = (const float*)d_in[15];
    const float* vm   = (const float*)d_in[16];
    const float* vv   = (const float*)d_in[17];
    const float* vpw  = (const float*)d_in[18];
    const float* pos  = (const float*)d_in[19];
    const float* outw = (const float*)d_in[20];
    const float* outb = (const float*)d_in[21];
    float* out = (float*)d_out;

    static bool attr_done = false;
    if (!attr_done) {
        cudaFuncSetAttribute(gemm_qkv_kernel,
            cudaFuncAttributeMaxDynamicSharedMemorySize, GEMM_SMEM_BYTES);
        cudaFuncSetAttribute(gemm_out_kernel,
            cudaFuncAttributeMaxDynamicSharedMemorySize, GEMM_SMEM_BYTES);
        attr_done = true;
    }

    prep_w_kernel<<<2048, 256>>>(qpw, kpw, vpw, outw);

    int total = BATCH * DIMC * NPIX;
    dwbn_kernel<<<(total + 255) / 256, 256>>>(x,
        qdw, qg, qb, qm, qv,
        kdw, kg, kb, km, kv,
        vdw, vg, vb, vm, vv);

    gemm_qkv_kernel<<<dim3(25, 4, 48), 256, GEMM_SMEM_BYTES>>>();

    attn_kernel<<<dim3(NWIN, HEADS, BATCH), 128>>>(pos);

    gemm_out_kernel<<<dim3(25, 2, 16), 256, GEMM_SMEM_BYTES>>>(outb, out);
}

// round 6
// speedup vs baseline: 3.8500x; 1.1612x over previous
#include <cuda_runtime.h>
#include <cuda_bf16.h>
#include <cstdint>

#define DIMC   256
#define INNER  512
#define HEADS  8
#define DHEAD  64
#define WS     7
#define NTOK   49
#define HW     56
#define NPIX   3136      // 56*56, also 49*64
#define BATCH  16
#define NWIN   64        // 8*8 windows

// GEMM smem strides (words) — conflict-free fragment LDS
#define AST 36           // A tile row stride (32 data + 4 pad)
#define BST 136          // B tile row stride (128 data + 8 pad)
#define A_WORDS (128 * AST)   // 4608
#define B_WORDS (32 * BST)    // 4352
#define NSTAGE 3
#define GEMM_SMEM_BYTES ((NSTAGE * (A_WORDS + B_WORDS)) * 4)

// attention smem strides (words); all row strides are multiples of 4 -> 16B-aligned rows
#define QS_STR 68
#define KS_STR 68
#define VS_STR 72
#define PS_STR 60

// ---------------- scratch (device globals; no allocation allowed) ----------
__device__ __align__(128) float g_y[3L * BATCH * DIMC * NPIX];   // dw+bn out (tf32-rounded)
__device__ __align__(128) float g_qkv[3L * BATCH * INNER * NPIX];// tf32-rounded qkv
__device__ __align__(128) float g_a[(long)BATCH * INNER * NPIX]; // attn out (tf32-rounded)
__device__ __align__(128) float g_w[4L * 131072];                // tf32-rounded weights

// ---------------------------------------------------------------------------
__device__ __forceinline__ uint32_t f2tf32(float x) {
    uint32_t r;
    asm("cvt.rna.tf32.f32 %0, %1;" : "=r"(r) : "f"(x));
    return r;
}

__device__ __forceinline__ void mma_tf32(float4& d, const uint32_t a[4],
                                         const uint32_t b[2], const float4& c) {
    asm volatile(
        "mma.sync.aligned.m16n8k8.row.col.f32.tf32.tf32.f32 "
        "{%0,%1,%2,%3}, {%4,%5,%6,%7}, {%8,%9}, {%10,%11,%12,%13};\n"
        : "=f"(d.x), "=f"(d.y), "=f"(d.z), "=f"(d.w)
        : "r"(a[0]), "r"(a[1]), "r"(a[2]), "r"(a[3]),
          "r"(b[0]), "r"(b[1]),
          "f"(c.x), "f"(c.y), "f"(c.z), "f"(c.w));
}

__device__ __forceinline__ void cpa16(uint32_t dst, const void* src) {
    asm volatile("cp.async.cg.shared.global [%0], [%1], 16;\n"
                 :: "r"(dst), "l"(src));
}
__device__ __forceinline__ void cpa16z(uint32_t dst, const void* src, bool ok) {
    int sz = ok ? 16 : 0;
    asm volatile("cp.async.cg.shared.global [%0], [%1], 16, %2;\n"
                 :: "r"(dst), "l"(src), "r"(sz));
}

// issue one k-tile stage (A 128x32, B 32x128) via cp.async + commit
__device__ __forceinline__ void gemm_stage(const float* __restrict__ A,
                                           const float* __restrict__ B,
                                           int K, int m0, int n0, int k0,
                                           uint32_t sa, uint32_t sb, int tid)
{
    #pragma unroll
    for (int r = 0; r < 4; r++) {
        int idx = tid + r * 256;
        int row = idx >> 3, cc = idx & 7;
        cpa16(sa + (row * AST + cc * 4) * 4,
              &A[(long)(m0 + row) * K + k0 + cc * 4]);
    }
    #pragma unroll
    for (int r = 0; r < 4; r++) {
        int idx = tid + r * 256;
        int row = idx >> 5, cc = idx & 31;
        int n = n0 + cc * 4;
        cpa16z(sb + (row * BST + cc * 4) * 4,
               &B[(long)(k0 + row) * NPIX + n], n < NPIX);
    }
    asm volatile("cp.async.commit_group;\n" ::: "memory");
}

// pipelined tf32 GEMM core
__device__ __forceinline__ void gemm_core(
    const float* __restrict__ A, const float* __restrict__ B,
    int K, int m0, int n0, float* smA, float* smB, float4 acc[4][4])
{
    const int tid = threadIdx.x;
    const int lane = tid & 31, warp = tid >> 5;
    const int wm = warp >> 2, wn = warp & 3;
    const int gi = lane >> 2, li = lane & 3;

    #pragma unroll
    for (int i = 0; i < 4; i++)
        #pragma unroll
        for (int j = 0; j < 4; j++) acc[i][j] = make_float4(0.f, 0.f, 0.f, 0.f);

    uint32_t saB = (uint32_t)__cvta_generic_to_shared(smA);
    uint32_t sbB = (uint32_t)__cvta_generic_to_shared(smB);

    const int nk = K >> 5;
    gemm_stage(A, B, K, m0, n0, 0, saB, sbB, tid);
    gemm_stage(A, B, K, m0, n0, 32, saB + A_WORDS * 4, sbB + B_WORDS * 4, tid);

    for (int kt = 0; kt < nk; kt++) {
        if (kt + 1 < nk)
            asm volatile("cp.async.wait_group 1;\n" ::: "memory");
        else
            asm volatile("cp.async.wait_group 0;\n" ::: "memory");
        __syncthreads();

        const float* As = smA + (kt % NSTAGE) * A_WORDS;
        const float* Bs = smB + (kt % NSTAGE) * B_WORDS;

        #pragma unroll
        for (int ks = 0; ks < 4; ks++) {
            uint32_t bf[4][2];
            #pragma unroll
            for (int j = 0; j < 4; j++) {
                int n = wn * 32 + j * 8 + gi;
                bf[j][0] = __float_as_uint(Bs[(ks * 8 + li) * BST + n]);
                bf[j][1] = __float_as_uint(Bs[(ks * 8 + li + 4) * BST + n]);
            }
            #pragma unroll
            for (int i = 0; i < 4; i++) {
                int rlo = wm * 64 + i * 16 + gi;
                uint32_t af[4];
                af[0] = __float_as_uint(As[rlo * AST + ks * 8 + li]);
                af[1] = __float_as_uint(As[(rlo + 8) * AST + ks * 8 + li]);
                af[2] = __float_as_uint(As[rlo * AST + ks * 8 + li + 4]);
                af[3] = __float_as_uint(As[(rlo + 8) * AST + ks * 8 + li + 4]);
                #pragma unroll
                for (int j = 0; j < 4; j++)
                    mma_tf32(acc[i][j], af, bf[j], acc[i][j]);
            }
        }

        if (kt + 2 < nk) {
            int s = (kt + 2) % NSTAGE;
            gemm_stage(A, B, K, m0, n0, (kt + 2) * 32,
                       saB + s * A_WORDS * 4, sbB + s * B_WORDS * 4, tid);
        }
    }
}

// ---------------------------------------------------------------------------
// Kernel 0: round all weights to tf32 once
// ---------------------------------------------------------------------------
__global__ void prep_w_kernel(const float* __restrict__ pwq,
                              const float* __restrict__ pwk,
                              const float* __restrict__ pwv,
                              const float* __restrict__ wo)
{
    int i = blockIdx.x * 256 + threadIdx.x;
    if (i >= 4 * 131072) return;
    float v;
    if (i < 131072)       v = pwq[i];
    else if (i < 262144)  v = pwk[i - 131072];
    else if (i < 393216)  v = pwv[i - 262144];
    else                  v = wo[i - 393216];
    g_w[i] = __uint_as_float(f2tf32(v));
}

// ---------------------------------------------------------------------------
// Kernel 1: depthwise 3x3 conv + BN, 4 pixels per thread, tf32-rounded out
// ---------------------------------------------------------------------------
__global__ __launch_bounds__(256) void dwbn_kernel(const float* __restrict__ x,
    const float* __restrict__ qdw, const float* __restrict__ qg,
    const float* __restrict__ qb,  const float* __restrict__ qm,
    const float* __restrict__ qv,
    const float* __restrict__ kdw, const float* __restrict__ kg,
    const float* __restrict__ kb,  const float* __restrict__ km,
    const float* __restrict__ kv,
    const float* __restrict__ vdw, const float* __restrict__ vg,
    const float* __restrict__ vb,  const float* __restrict__ vm,
    const float* __restrict__ vv)
{
    const int NSTRIP = NPIX / 4;   // 784
    int idx = blockIdx.x * blockDim.x + threadIdx.x;
    if (idx >= BATCH * DIMC * NSTRIP) return;
    int s = idx % NSTRIP;
    int c = (idx / NSTRIP) % DIMC;
    int b = idx / (NSTRIP * DIMC);
    int p0 = s * 4;
    int yy = p0 / HW, xx0 = p0 % HW;   // xx0 in {0,4,...,52}; strip is row-contained

    float wq[9], wk[9], wv[9];
    #pragma unroll
    for (int t = 0; t < 9; t++) {
        wq[t] = __ldg(&qdw[c * 9 + t]);
        wk[t] = __ldg(&kdw[c * 9 + t]);
        wv[t] = __ldg(&vdw[c * 9 + t]);
    }

    const float* xb = x + ((long)(b * DIMC + c)) * NPIX;
    float aq[4] = {0.f, 0.f, 0.f, 0.f};
    float ak[4] = {0.f, 0.f, 0.f, 0.f};
    float av[4] = {0.f, 0.f, 0.f, 0.f};

    #pragma unroll
    for (int ky = 0; ky < 3; ky++) {
        int iy = yy + ky - 1;
        if (iy < 0 || iy >= HW) continue;
        const float* row = xb + iy * HW;
        float v[6];
        v[0] = (xx0 > 0) ? row[xx0 - 1] : 0.f;
        float4 mid = *(const float4*)&row[xx0];
        v[1] = mid.x; v[2] = mid.y; v[3] = mid.z; v[4] = mid.w;
        v[5] = (xx0 + 4 < HW) ? row[xx0 + 4] : 0.f;
        #pragma unroll
        for (int px = 0; px < 4; px++) {
            #pragma unroll
            for (int kx = 0; kx < 3; kx++) {
                float xv = v[px + kx];
                aq[px] += xv * wq[ky * 3 + kx];
                ak[px] += xv * wk[ky * 3 + kx];
                av[px] += xv * wv[ky * 3 + kx];
            }
        }
    }
    float sq = __ldg(&qg[c]) * rsqrtf(__ldg(&qv[c]) + 1e-5f);
    float sk = __ldg(&kg[c]) * rsqrtf(__ldg(&kv[c]) + 1e-5f);
    float sv = __ldg(&vg[c]) * rsqrtf(__ldg(&vv[c]) + 1e-5f);
    float mq = __ldg(&qm[c]), bq = __ldg(&qb[c]);
    float mk = __ldg(&km[c]), bk = __ldg(&kb[c]);
    float mv = __ldg(&vm[c]), bv = __ldg(&vb[c]);

    long base = ((long)b * DIMC + c) * NPIX + p0;
    const long pstride = (long)BATCH * DIMC * NPIX;
    float4 oq, ok, ov;
    float* oqp = (float*)&oq; float* okp = (float*)&ok; float* ovp = (float*)&ov;
    #pragma unroll
    for (int px = 0; px < 4; px++) {
        oqp[px] = __uint_as_float(f2tf32((aq[px] - mq) * sq + bq));
        okp[px] = __uint_as_float(f2tf32((ak[px] - mk) * sk + bk));
        ovp[px] = __uint_as_float(f2tf32((av[px] - mv) * sv + bv));
    }
    *(float4*)&g_y[base]               = oq;
    *(float4*)&g_y[base + pstride]     = ok;
    *(float4*)&g_y[base + 2 * pstride] = ov;
}

// ---------------------------------------------------------------------------
// Kernel 2: qkv pointwise conv 256->512, pipelined tf32 GEMM.
// epilogue rounds to tf32 so attn can load raw.
// ---------------------------------------------------------------------------
__global__ __launch_bounds__(256) void gemm_qkv_kernel()
{
    extern __shared__ __align__(16) float smem[];
    float* smA = smem;
    float* smB = smem + NSTAGE * A_WORDS;

    int z = blockIdx.z;
    int proj = z >> 4;
    int b = z & 15;
    const float* A = g_w + (long)proj * 131072;          // [512,256] tf32
    const float* B = g_y + ((long)proj * BATCH + b) * DIMC * NPIX;

    int m0 = blockIdx.y * 128;
    int n0 = blockIdx.x * 128;

    float4 acc[4][4];
    gemm_core(A, B, DIMC, m0, n0, smA, smB, acc);

    const int lane = threadIdx.x & 31, warp = threadIdx.x >> 5;
    const int wm = warp >> 2, wn = warp & 3;
    const int gid = lane >> 2, tig = lane & 3;
    float* dst = g_qkv + ((long)proj * BATCH + b) * HEADS * NWIN * NPIX;

    #pragma unroll
    for (int i = 0; i < 4; i++) {
        int o_lo = m0 + wm * 64 + i * 16 + gid;
        int o_hi = o_lo + 8;
        #pragma unroll
        for (int j = 0; j < 4; j++) {
            int p0 = n0 + wn * 32 + j * 8 + tig * 2;
            int p1 = p0 + 1;
            float vals[4] = {acc[i][j].x, acc[i][j].y, acc[i][j].z, acc[i][j].w};
            int os[4] = {o_lo, o_lo, o_hi, o_hi};
            int ps[4] = {p0, p1, p0, p1};
            #pragma unroll
            for (int e = 0; e < 4; e++) {
                int p = ps[e];
                if (p < NPIX) {
                    int o = os[e];
                    int h = o >> 6, dd = o & 63;
                    int yy = p / HW, xx = p % HW;
                    int w = (yy / WS) * 8 + (xx / WS);
                    int t = (yy % WS) * WS + (xx % WS);
                    dst[((long)(h * NWIN + w)) * NPIX + t * 64 + dd] =
                        __uint_as_float(f2tf32(vals[e]));
                }
            }
        }
    }
}

// ---------------------------------------------------------------------------
// Kernel 3: windowed attention on tensor cores; cp.async staging (inputs
// pre-rounded to tf32 by gemm_qkv).
// ---------------------------------------------------------------------------
__global__ __launch_bounds__(128) void attn_kernel(const float* __restrict__ pos_emb)
{
    __shared__ __align__(16) uint32_t Qs[64 * QS_STR];   // aliased as Ps in phase 2
    __shared__ __align__(16) uint32_t Ks[56 * KS_STR];
    __shared__ __align__(16) uint32_t Vs[56 * VS_STR];
    uint32_t* Ps = Qs;

    int w = blockIdx.x, h = blockIdx.y, b = blockIdx.z;
    int tid = threadIdx.x;
    int lane = tid & 31, warp = tid >> 5;
    int gi = lane >> 2, li = lane & 3;

    const long pstride = (long)BATCH * INNER * NPIX;
    long base = (((long)b * HEADS + h) * NWIN + w) * NPIX;
    const float* gq = g_qkv + base;
    const float* gk = g_qkv + base + pstride;
    const float* gv = g_qkv + base + 2 * pstride;

    uint32_t sQ = (uint32_t)__cvta_generic_to_shared(Qs);
    uint32_t sK = (uint32_t)__cvta_generic_to_shared(Ks);
    uint32_t sV = (uint32_t)__cvta_generic_to_shared(Vs);

    // zero K/V pad rows 49..55 (regular STS; completes before the barrier)
    for (int i = tid; i < 7 * 64; i += 128) {
        int t = NTOK + (i >> 6), d = i & 63;
        Ks[t * KS_STR + d] = 0;
        Vs[t * VS_STR + d] = 0;
    }
    // async-stage Q/K/V as 16B chunks (784 chunks each)
    for (int i = tid; i < NTOK * 16; i += 128) {
        int t = i >> 4, dq = (i & 15) * 4;
        cpa16(sQ + (t * QS_STR + dq) * 4, gq + t * 64 + dq);
        cpa16(sK + (t * KS_STR + dq) * 4, gk + t * 64 + dq);
        cpa16(sV + (t * VS_STR + dq) * 4, gv + t * 64 + dq);
    }
    asm volatile("cp.async.commit_group;\n" ::: "memory");
    asm volatile("cp.async.wait_group 0;\n" ::: "memory");
    __syncthreads();

    int row_lo = warp * 16 + gi;
    int row_hi = row_lo + 8;

    // ---- phase 1: S = Q K^T ----
    uint32_t a[8][4];
    #pragma unroll
    for (int kk = 0; kk < 8; kk++) {
        a[kk][0] = Qs[row_lo * QS_STR + kk * 8 + li];
        a[kk][1] = Qs[row_hi * QS_STR + kk * 8 + li];
        a[kk][2] = Qs[row_lo * QS_STR + kk * 8 + li + 4];
        a[kk][3] = Qs[row_hi * QS_STR + kk * 8 + li + 4];
    }
    float4 c[7];
    #pragma unroll
    for (int j = 0; j < 7; j++) {
        c[j] = make_float4(0.f, 0.f, 0.f, 0.f);
        #pragma unroll
        for (int kk = 0; kk < 8; kk++) {
            uint32_t bf[2];
            bf[0] = Ks[(j * 8 + gi) * KS_STR + kk * 8 + li];
            bf[1] = Ks[(j * 8 + gi) * KS_STR + kk * 8 + li + 4];
            mma_tf32(c[j], a[kk], bf, c[j]);
        }
    }

    // ---- bias + softmax in registers ----
    int rr_lo = row_lo / 7, rc_lo = row_lo % 7;
    int rr_hi = row_hi / 7, rc_hi = row_hi % 7;
    float vlo[14], vhi[14];
    #pragma unroll
    for (int j = 0; j < 7; j++) {
        #pragma unroll
        for (int e = 0; e < 2; e++) {
            int col = j * 8 + li * 2 + e;
            float s_lo = (e == 0) ? c[j].x : c[j].y;
            float s_hi = (e == 0) ? c[j].z : c[j].w;
            if (col < NTOK) {
                int cr = col / 7, cc = col % 7;
                int rel_lo = (cr - rr_lo + 6) * 13 + (cc - rc_lo + 6);
                int rel_hi = (cr - rr_hi + 6) * 13 + (cc - rc_hi + 6);
                rel_lo = min(max(rel_lo, 0), 168);
                rel_hi = min(max(rel_hi, 0), 168);
                vlo[j * 2 + e] = fmaf(s_lo, 0.125f, __ldg(&pos_emb[rel_lo * HEADS + h]));
                vhi[j * 2 + e] = fmaf(s_hi, 0.125f, __ldg(&pos_emb[rel_hi * HEADS + h]));
            } else {
                vlo[j * 2 + e] = -1e30f;
                vhi[j * 2 + e] = -1e30f;
            }
        }
    }
    float mlo = -1e30f, mhi = -1e30f;
    #pragma unroll
    for (int i = 0; i < 14; i++) { mlo = fmaxf(mlo, vlo[i]); mhi = fmaxf(mhi, vhi[i]); }
    mlo = fmaxf(mlo, __shfl_xor_sync(0xffffffffu, mlo, 1));
    mlo = fmaxf(mlo, __shfl_xor_sync(0xffffffffu, mlo, 2));
    mhi = fmaxf(mhi, __shfl_xor_sync(0xffffffffu, mhi, 1));
    mhi = fmaxf(mhi, __shfl_xor_sync(0xffffffffu, mhi, 2));
    float slo = 0.f, shi = 0.f;
    #pragma unroll
    for (int i = 0; i < 14; i++) {
        vlo[i] = __expf(vlo[i] - mlo); slo += vlo[i];
        vhi[i] = __expf(vhi[i] - mhi); shi += vhi[i];
    }
    slo += __shfl_xor_sync(0xffffffffu, slo, 1);
    slo += __shfl_xor_sync(0xffffffffu, slo, 2);
    shi += __shfl_xor_sync(0xffffffffu, shi, 1);
    shi += __shfl_xor_sync(0xffffffffu, shi, 2);
    float ilo = 1.f / slo, ihi = 1.f / shi;

    __syncthreads();
    #pragma unroll
    for (int j = 0; j < 7; j++) {
        #pragma unroll
        for (int e = 0; e < 2; e++) {
            int col = j * 8 + li * 2 + e;
            Ps[row_lo * PS_STR + col] = f2tf32(vlo[j * 2 + e] * ilo);
            Ps[row_hi * PS_STR + col] = f2tf32(vhi[j * 2 + e] * ihi);
        }
    }
    __syncthreads();

    // ---- phase 2: O = P V ----
    uint32_t pa[7][4];
    #pragma unroll
    for (int kk = 0; kk < 7; kk++) {
        pa[kk][0] = Ps[row_lo * PS_STR + kk * 8 + li];
        pa[kk][1] = Ps[row_hi * PS_STR + kk * 8 + li];
        pa[kk][2] = Ps[row_lo * PS_STR + kk * 8 + li + 4];
        pa[kk][3] = Ps[row_hi * PS_STR + kk * 8 + li + 4];
    }
    float* ga = g_a + ((long)b * INNER + h * 64) * NPIX + (long)w * NTOK;
    #pragma unroll
    for (int dn = 0; dn < 8; dn++) {
        float4 o = make_float4(0.f, 0.f, 0.f, 0.f);
        #pragma unroll
        for (int kk = 0; kk < 7; kk++) {
            uint32_t bf[2];
            bf[0] = Vs[(kk * 8 + li) * VS_STR + dn * 8 + gi];
            bf[1] = Vs[(kk * 8 + li + 4) * VS_STR + dn * 8 + gi];
            mma_tf32(o, pa[kk], bf, o);
        }
        int d0 = dn * 8 + li * 2;
        if (row_lo < NTOK) {
            ga[(long)d0 * NPIX + row_lo]       = __uint_as_float(f2tf32(o.x));
            ga[(long)(d0 + 1) * NPIX + row_lo] = __uint_as_float(f2tf32(o.y));
        }
        if (row_hi < NTOK) {
            ga[(long)d0 * NPIX + row_hi]       = __uint_as_float(f2tf32(o.z));
            ga[(long)(d0 + 1) * NPIX + row_hi] = __uint_as_float(f2tf32(o.w));
        }
    }
}

// ---------------------------------------------------------------------------
// Kernel 4: out-projection 512->256 pipelined tf32 GEMM + bias, un-window
// ---------------------------------------------------------------------------
__global__ __launch_bounds__(256) void gemm_out_kernel(
    const float* __restrict__ ob, float* __restrict__ out)
{
    extern __shared__ __align__(16) float smem[];
    float* smA = smem;
    float* smB = smem + NSTAGE * A_WORDS;

    int b = blockIdx.z;
    const float* A = g_w + 3L * 131072;                  // [256,512] tf32
    const float* B = g_a + (long)b * INNER * NPIX;

    int m0 = blockIdx.y * 128;
    int n0 = blockIdx.x * 128;

    float4 acc[4][4];
    gemm_core(A, B, INNER, m0, n0, smA, smB, acc);

    const int lane = threadIdx.x & 31, warp = threadIdx.x >> 5;
    const int wm = warp >> 2, wn = warp & 3;
    const int gid = lane >> 2, tig = lane & 3;

    #pragma unroll
    for (int i = 0; i < 4; i++) {
        int o_lo = m0 + wm * 64 + i * 16 + gid;
        int o_hi = o_lo + 8;
        float bias_lo = __ldg(&ob[o_lo]);
        float bias_hi = __ldg(&ob[o_hi]);
        #pragma unroll
        for (int j = 0; j < 4; j++) {
            int p0 = n0 + wn * 32 + j * 8 + tig * 2;
            int p1 = p0 + 1;
            float vals[4] = {acc[i][j].x + bias_lo, acc[i][j].y + bias_lo,
                             acc[i][j].z + bias_hi, acc[i][j].w + bias_hi};
            int os[4] = {o_lo, o_lo, o_hi, o_hi};
            int ps[4] = {p0, p1, p0, p1};
            #pragma unroll
            for (int e = 0; e < 4; e++) {
                int p = ps[e];
                if (p < NPIX) {
                    int o = os[e];
                    int w = p / NTOK, t = p % NTOK;
                    int yy = (w / 8) * WS + t / WS;
                    int xx = (w % 8) * WS + t % WS;
                    out[((long)b * DIMC + o) * NPIX + yy * HW + xx] = vals[e];
                }
            }
        }
    }
}

// ---------------------------------------------------------------------------
extern "C" void kernel_launch(void* const* d_in, const int* in_sizes, int n_in,
                              void* d_out, int out_size)
{
    const float* x    = (const float*)d_in[0];
    const float* qdw  = (const float*)d_in[1];
    const float* qg   = (const float*)d_in[2];
    const float* qb   = (const float*)d_in[3];
    const float* qm   = (const float*)d_in[4];
    const float* qv   = (const float*)d_in[5];
    const float* qpw  = (const float*)d_in[6];
    const float* kdw  = (const float*)d_in[7];
    const float* kg   = (const float*)d_in[8];
    const float* kb   = (const float*)d_in[9];
    const float* km   = (const float*)d_in[10];
    const float* kv   = (const float*)d_in[11];
    const float* kpw  = (const float*)d_in[12];
    const float* vdw  = (const float*)d_in[13];
    const float* vg   = (const float*)d_in[14];
    const float* vb   = (const float*)d_in[15];
    const float* vm   = (const float*)d_in[16];
    const float* vv   = (const float*)d_in[17];
    const float* vpw  = (const float*)d_in[18];
    const float* pos  = (const float*)d_in[19];
    const float* outw = (const float*)d_in[20];
    const float* outb = (const float*)d_in[21];
    float* out = (float*)d_out;

    static bool attr_done = false;
    if (!attr_done) {
        cudaFuncSetAttribute(gemm_qkv_kernel,
            cudaFuncAttributeMaxDynamicSharedMemorySize, GEMM_SMEM_BYTES);
        cudaFuncSetAttribute(gemm_out_kernel,
            cudaFuncAttributeMaxDynamicSharedMemorySize, GEMM_SMEM_BYTES);
        attr_done = true;
    }

    prep_w_kernel<<<2048, 256>>>(qpw, kpw, vpw, outw);

    int nstrips = BATCH * DIMC * (NPIX / 4);
    dwbn_kernel<<<(nstrips + 255) / 256, 256>>>(x,
        qdw, qg, qb, qm, qv,
        kdw, kg, kb, km, kv,
        vdw, vg, vb, vm, vv);

    gemm_qkv_kernel<<<dim3(25, 4, 48), 256, GEMM_SMEM_BYTES>>>();

    attn_kernel<<<dim3(NWIN, HEADS, BATCH), 128>>>(pos);

    gemm_out_kernel<<<dim3(25, 2, 16), 256, GEMM_SMEM_BYTES>>>(outb, out);
}